// round 1
// baseline (speedup 1.0000x reference)
#include <cuda_runtime.h>
#include <math_constants.h>

#define Bn 8
#define Ln 2048
#define Dn 64
#define BQ 64
#define BK 64
#define NTH 128
#define KST 68   // padded smem stride (floats) for qs / kt / vs
#define PST 64   // smem stride for probability tiles

// Flash-style fused bidirectional attention.
// CTA = (query tile of 64 rows, batch). 128 threads: ty=tid>>3 (16 row-groups
// of 4 rows), tx=tid&7 (8 col-groups of 8 cols). Each thread owns a 4x8
// register tile of scores and a 4x8 fp32 accumulator per direction.
__global__ __launch_bounds__(NTH, 2)
void attn_fwbw_kernel(const float* __restrict__ Q, const float* __restrict__ K,
                      const float* __restrict__ V, float* __restrict__ O)
{
    extern __shared__ float smem[];
    float* qs = smem;                    // [BQ][KST]  (pre-scaled by 1/sqrt(D))
    float* kt = qs + BQ * KST;           // [Dn][KST]  K transposed: kt[d][c]
    float* vs = kt + Dn * KST;           // [BK][KST]  vs[j][d]
    float* pf = vs + BK * KST;           // [BQ][PST]  fw probabilities
    float* pb = pf + BQ * PST;           // [BQ][PST]  bw probabilities

    const int b   = blockIdx.y;
    const int q0  = blockIdx.x * BQ;
    const int tid = threadIdx.x;
    const int ty  = tid >> 3;            // 0..15
    const int tx  = tid & 7;             // 0..7
    const int row0 = q0 + ty * 4;        // first global query row of this thread

    // ---- load Q tile, pre-scaled ----
    const float4* qg = reinterpret_cast<const float4*>(Q + (size_t)(b * Ln + q0) * Dn);
    #pragma unroll
    for (int i = tid; i < BQ * Dn / 4; i += NTH) {
        int r = i >> 4, c = i & 15;      // 16 float4 per row
        float4 t = qg[r * 16 + c];
        t.x *= 0.125f; t.y *= 0.125f; t.z *= 0.125f; t.w *= 0.125f;
        *reinterpret_cast<float4*>(&qs[r * KST + c * 4]) = t;
    }

    // ---- per-row online-softmax state (replicated across the 8 tx lanes) ----
    float m_f[4], l_f[4], m_b[4], l_b[4];
    float af[4][8], ab[4][8];
    #pragma unroll
    for (int r = 0; r < 4; r++) {
        m_f[r] = -CUDART_INF_F; l_f[r] = 0.f;
        m_b[r] = -CUDART_INF_F; l_b[r] = 0.f;
        #pragma unroll
        for (int c = 0; c < 8; c++) { af[r][c] = 0.f; ab[r][c] = 0.f; }
    }

    for (int j0 = 0; j0 < Ln; j0 += BK) {
        // fw attends j>=i: active iff tile not strictly below diagonal.
        // bw attends j<=i: active iff tile not strictly above diagonal.
        const bool do_f = (j0 >= q0);
        const bool do_b = (j0 <= q0);
        const bool diag = (j0 == q0);

        // ---- load K (transposed) and V tiles ----
        __syncthreads();   // previous iteration done with kt/vs
        {
            const float4* kg = reinterpret_cast<const float4*>(K + (size_t)(b * Ln + j0) * Dn);
            const float4* vg = reinterpret_cast<const float4*>(V + (size_t)(b * Ln + j0) * Dn);
            #pragma unroll
            for (int i = tid; i < BK * Dn / 4; i += NTH) {
                int r = i >> 4, c = i & 15;
                float4 kv = kg[r * 16 + c];
                kt[(c * 4 + 0) * KST + r] = kv.x;
                kt[(c * 4 + 1) * KST + r] = kv.y;
                kt[(c * 4 + 2) * KST + r] = kv.z;
                kt[(c * 4 + 3) * KST + r] = kv.w;
                *reinterpret_cast<float4*>(&vs[r * KST + c * 4]) = vg[r * 16 + c];
            }
        }
        __syncthreads();

        // ---- score GEMM: s[4][8] = (Q*scale) @ K^T ----
        float s[4][8];
        #pragma unroll
        for (int r = 0; r < 4; r++)
            #pragma unroll
            for (int c = 0; c < 8; c++) s[r][c] = 0.f;

        #pragma unroll 8
        for (int d = 0; d < Dn; d++) {
            float4 k0 = *reinterpret_cast<const float4*>(&kt[d * KST + tx * 8]);
            float4 k1 = *reinterpret_cast<const float4*>(&kt[d * KST + tx * 8 + 4]);
            #pragma unroll
            for (int r = 0; r < 4; r++) {
                float qv = qs[(ty * 4 + r) * KST + d];
                s[r][0] += qv * k0.x; s[r][1] += qv * k0.y;
                s[r][2] += qv * k0.z; s[r][3] += qv * k0.w;
                s[r][4] += qv * k1.x; s[r][5] += qv * k1.y;
                s[r][6] += qv * k1.z; s[r][7] += qv * k1.w;
            }
        }

        // ---- online softmax updates (fw then bw) ----
        if (do_f) {
            #pragma unroll
            for (int r = 0; r < 4; r++) {
                float sv[8];
                float rmax = -CUDART_INF_F;
                #pragma unroll
                for (int c = 0; c < 8; c++) {
                    float val = s[r][c];
                    if (diag && (j0 + tx * 8 + c) < (row0 + r)) val = -CUDART_INF_F;
                    sv[c] = val;
                    rmax = fmaxf(rmax, val);
                }
                #pragma unroll
                for (int o = 1; o < 8; o <<= 1)
                    rmax = fmaxf(rmax, __shfl_xor_sync(0xffffffffu, rmax, o));
                float mnew = fmaxf(m_f[r], rmax);
                float corr = __expf(m_f[r] - mnew);
                m_f[r] = mnew;
                float psum = 0.f;
                #pragma unroll
                for (int c = 0; c < 8; c++) {
                    float p = __expf(sv[c] - mnew);   // masked -> exp(-inf) = 0
                    pf[(ty * 4 + r) * PST + tx * 8 + c] = p;
                    psum += p;
                }
                #pragma unroll
                for (int o = 1; o < 8; o <<= 1)
                    psum += __shfl_xor_sync(0xffffffffu, psum, o);
                l_f[r] = l_f[r] * corr + psum;
                #pragma unroll
                for (int c = 0; c < 8; c++) af[r][c] *= corr;
            }
        }
        if (do_b) {
            #pragma unroll
            for (int r = 0; r < 4; r++) {
                float sv[8];
                float rmax = -CUDART_INF_F;
                #pragma unroll
                for (int c = 0; c < 8; c++) {
                    float val = s[r][c];
                    if (diag && (j0 + tx * 8 + c) > (row0 + r)) val = -CUDART_INF_F;
                    sv[c] = val;
                    rmax = fmaxf(rmax, val);
                }
                #pragma unroll
                for (int o = 1; o < 8; o <<= 1)
                    rmax = fmaxf(rmax, __shfl_xor_sync(0xffffffffu, rmax, o));
                float mnew = fmaxf(m_b[r], rmax);
                float corr = __expf(m_b[r] - mnew);
                m_b[r] = mnew;
                float psum = 0.f;
                #pragma unroll
                for (int c = 0; c < 8; c++) {
                    float p = __expf(sv[c] - mnew);
                    pb[(ty * 4 + r) * PST + tx * 8 + c] = p;
                    psum += p;
                }
                #pragma unroll
                for (int o = 1; o < 8; o <<= 1)
                    psum += __shfl_xor_sync(0xffffffffu, psum, o);
                l_b[r] = l_b[r] * corr + psum;
                #pragma unroll
                for (int c = 0; c < 8; c++) ab[r][c] *= corr;
            }
        }

        // Each warp consumes exactly the P rows it produced (rows 16w..16w+15),
        // so a warp-level sync is sufficient here.
        __syncwarp();

        // ---- PV GEMM: acc[r][0..7] += P[r][j] * V[j][tx*8 .. tx*8+7] ----
        #pragma unroll 4
        for (int j = 0; j < BK; j++) {
            float4 v0 = *reinterpret_cast<const float4*>(&vs[j * KST + tx * 8]);
            float4 v1 = *reinterpret_cast<const float4*>(&vs[j * KST + tx * 8 + 4]);
            #pragma unroll
            for (int r = 0; r < 4; r++) {
                if (do_f) {
                    float p = pf[(ty * 4 + r) * PST + j];
                    af[r][0] += p * v0.x; af[r][1] += p * v0.y;
                    af[r][2] += p * v0.z; af[r][3] += p * v0.w;
                    af[r][4] += p * v1.x; af[r][5] += p * v1.y;
                    af[r][6] += p * v1.z; af[r][7] += p * v1.w;
                }
                if (do_b) {
                    float p = pb[(ty * 4 + r) * PST + j];
                    ab[r][0] += p * v0.x; ab[r][1] += p * v0.y;
                    ab[r][2] += p * v0.z; ab[r][3] += p * v0.w;
                    ab[r][4] += p * v1.x; ab[r][5] += p * v1.y;
                    ab[r][6] += p * v1.z; ab[r][7] += p * v1.w;
                }
            }
        }
        __syncwarp();
    }

    // ---- epilogue: out = acc_f / l_f + acc_b / l_b ----
    #pragma unroll
    for (int r = 0; r < 4; r++) {
        float inv_f = 1.f / l_f[r];     // diagonal always present -> l > 0
        float inv_b = 1.f / l_b[r];
        float4 o0, o1;
        o0.x = af[r][0] * inv_f + ab[r][0] * inv_b;
        o0.y = af[r][1] * inv_f + ab[r][1] * inv_b;
        o0.z = af[r][2] * inv_f + ab[r][2] * inv_b;
        o0.w = af[r][3] * inv_f + ab[r][3] * inv_b;
        o1.x = af[r][4] * inv_f + ab[r][4] * inv_b;
        o1.y = af[r][5] * inv_f + ab[r][5] * inv_b;
        o1.z = af[r][6] * inv_f + ab[r][6] * inv_b;
        o1.w = af[r][7] * inv_f + ab[r][7] * inv_b;
        float4* og = reinterpret_cast<float4*>(O + (size_t)(b * Ln + row0 + r) * Dn + tx * 8);
        og[0] = o0;
        og[1] = o1;
    }
}

extern "C" void kernel_launch(void* const* d_in, const int* in_sizes, int n_in,
                              void* d_out, int out_size) {
    const float* q = (const float*)d_in[0];
    const float* k = (const float*)d_in[1];
    const float* v = (const float*)d_in[2];
    float* o = (float*)d_out;

    const size_t smem_bytes =
        (size_t)(BQ * KST + Dn * KST + BK * KST + 2 * BQ * PST) * sizeof(float);
    cudaFuncSetAttribute(attn_fwbw_kernel,
                         cudaFuncAttributeMaxDynamicSharedMemorySize,
                         (int)smem_bytes);

    dim3 grid(Ln / BQ, Bn);
    attn_fwbw_kernel<<<grid, NTH, smem_bytes>>>(q, k, v, o);
}

// round 3
// speedup vs baseline: 2.0831x; 2.0831x over previous
#include <cuda_runtime.h>

#define Bn 8
#define Ln 2048
#define Dn 64
#define BQ 128
#define BK 128
#define NTH 256
#define ST 68     // qs/ks/vs row stride in floats (272 B = 16B-multiple, REQUIRED for float4)
#define PST 132   // p row stride (528 B, 16B-multiple)
#define NJT (Ln / BK)

// Fused bidirectional (causal + anti-causal) attention, flash-style.
// CTA = (128-query tile, batch); 256 threads as 16x16 grid:
//   ty = tid>>4 -> 8 query rows (ty*8 .. ty*8+7)
//   tx = tid&15 -> 8 key cols in QK^T (tx*8..), 4 output dims in PV (tx*4..)
// Two phases: phase 0 accumulates the causal (j>=i) softmax*V, writes O;
// phase 1 accumulates the anti-causal (j<=i) result and adds into O.
// All operands stay in natural [row][d] layout (no smem transposes).
__global__ __launch_bounds__(NTH, 1)
void attn_fwbw2(const float* __restrict__ Q, const float* __restrict__ K,
                const float* __restrict__ V, float* __restrict__ O)
{
    extern __shared__ float sm[];
    float* qs = sm;               // [BQ][ST]  pre-scaled Q
    float* ks = qs + BQ * ST;     // [BK][ST]  K, d-group swizzled by row's tx-group
    float* vs = ks + BK * ST;     // [BK][ST]  V natural
    float* pp = vs + BK * ST;     // [BQ][PST] probabilities, col-group swizzled by ty

    const int b   = blockIdx.y;
    const int t   = blockIdx.x;          // q-tile index 0..15
    const int q0  = t * BQ;
    const int tid = threadIdx.x;
    const int ty  = tid >> 4;            // 0..15
    const int tx  = tid & 15;            // 0..15

    // ---- load Q tile once, pre-scaled by 1/sqrt(64) ----
    {
        const float4* qg = reinterpret_cast<const float4*>(Q + (size_t)(b * Ln + q0) * Dn);
        #pragma unroll
        for (int i = tid; i < BQ * Dn / 4; i += NTH) {
            int r = i >> 4, c = i & 15;
            float4 x = qg[i];
            x.x *= 0.125f; x.y *= 0.125f; x.z *= 0.125f; x.w *= 0.125f;
            *reinterpret_cast<float4*>(&qs[r * ST + c * 4]) = x;
        }
    }

    float* outp = O + (size_t)(b * Ln + q0 + ty * 8) * Dn + tx * 4;

    float acc[8][4];
    float m[8], l[8];

    for (int phase = 0; phase < 2; phase++) {
        #pragma unroll
        for (int r = 0; r < 8; r++) {
            m[r] = -1e30f; l[r] = 0.f;
            #pragma unroll
            for (int c = 0; c < 4; c++) acc[r][c] = 0.f;
        }

        const int jt_beg = (phase == 0) ? t : 0;
        const int jt_end = (phase == 0) ? NJT : (t + 1);

        for (int jt = jt_beg; jt < jt_end; jt++) {
            const bool diag = (jt == t);

            __syncthreads();   // everyone done with ks/vs/pp from previous tile
            {
                const float4* kg = reinterpret_cast<const float4*>(K + (size_t)(b * Ln + jt * BK) * Dn);
                const float4* vg = reinterpret_cast<const float4*>(V + (size_t)(b * Ln + jt * BK) * Dn);
                #pragma unroll
                for (int i = tid; i < BK * Dn / 4; i += NTH) {
                    int r = i >> 4, c = i & 15;
                    // K: swizzle d-group index by (row>>3) to kill QK read conflicts
                    *reinterpret_cast<float4*>(&ks[r * ST + ((c ^ (r >> 3)) & 15) * 4]) = kg[i];
                    *reinterpret_cast<float4*>(&vs[r * ST + c * 4]) = vg[i];
                }
            }
            __syncthreads();

            // ---- score GEMM: s[8][8] = Qs @ K^T over 16 d-chunks of 4 ----
            float s[8][8];
            #pragma unroll
            for (int r = 0; r < 8; r++)
                #pragma unroll
                for (int c = 0; c < 8; c++) s[r][c] = 0.f;

            #pragma unroll 4
            for (int dc = 0; dc < 16; dc++) {
                float4 kf[8];
                #pragma unroll
                for (int c = 0; c < 8; c++)
                    kf[c] = *reinterpret_cast<const float4*>(
                        &ks[(tx * 8 + c) * ST + ((dc ^ tx) & 15) * 4]);
                #pragma unroll
                for (int r = 0; r < 8; r++) {
                    float4 qf = *reinterpret_cast<const float4*>(
                        &qs[(ty * 8 + r) * ST + dc * 4]);
                    #pragma unroll
                    for (int c = 0; c < 8; c++) {
                        float v0 = s[r][c];
                        v0 = fmaf(qf.x, kf[c].x, v0);
                        v0 = fmaf(qf.y, kf[c].y, v0);
                        v0 = fmaf(qf.z, kf[c].z, v0);
                        v0 = fmaf(qf.w, kf[c].w, v0);
                        s[r][c] = v0;
                    }
                }
            }

            // ---- online softmax (one direction per phase) ----
            #pragma unroll
            for (int r = 0; r < 8; r++) {
                const int lr = ty * 8 + r;
                float rmax = -1e30f;
                #pragma unroll
                for (int c = 0; c < 8; c++) {
                    const int lc = tx * 8 + c;
                    const bool msk = diag && ((phase == 0) ? (lc < lr) : (lc > lr));
                    if (msk) s[r][c] = -1e30f;       // exp -> 0
                    rmax = fmaxf(rmax, s[r][c]);
                }
                #pragma unroll
                for (int o = 1; o < 16; o <<= 1)     // reduce over the 16 tx lanes
                    rmax = fmaxf(rmax, __shfl_xor_sync(0xffffffffu, rmax, o));

                const float mnew = fmaxf(m[r], rmax);
                const float corr = __expf(m[r] - mnew);
                m[r] = mnew;

                float pv[8], ps = 0.f;
                #pragma unroll
                for (int c = 0; c < 8; c++) { pv[c] = __expf(s[r][c] - mnew); ps += pv[c]; }

                const int prow = lr * PST;
                *reinterpret_cast<float4*>(&pp[prow + (((2 * tx)     ^ ty) & 31) * 4]) =
                    make_float4(pv[0], pv[1], pv[2], pv[3]);
                *reinterpret_cast<float4*>(&pp[prow + (((2 * tx + 1) ^ ty) & 31) * 4]) =
                    make_float4(pv[4], pv[5], pv[6], pv[7]);

                #pragma unroll
                for (int o = 1; o < 16; o <<= 1)
                    ps += __shfl_xor_sync(0xffffffffu, ps, o);
                l[r] = l[r] * corr + ps;
                #pragma unroll
                for (int c = 0; c < 4; c++) acc[r][c] *= corr;
            }
            // Each p row is written and read by the same 16 threads (same ty),
            // all inside one warp -> warp-level sync suffices.
            __syncwarp();

            // ---- PV GEMM: acc[r][0..3] += sum_j p[r][j] * V[j][tx*4..+3] ----
            #pragma unroll 2
            for (int jc = 0; jc < 32; jc++) {
                const int j = jc * 4;
                float4 v0 = *reinterpret_cast<const float4*>(&vs[(j + 0) * ST + tx * 4]);
                float4 v1 = *reinterpret_cast<const float4*>(&vs[(j + 1) * ST + tx * 4]);
                float4 v2 = *reinterpret_cast<const float4*>(&vs[(j + 2) * ST + tx * 4]);
                float4 v3 = *reinterpret_cast<const float4*>(&vs[(j + 3) * ST + tx * 4]);
                #pragma unroll
                for (int r = 0; r < 8; r++) {
                    float4 pf = *reinterpret_cast<const float4*>(
                        &pp[(ty * 8 + r) * PST + ((jc ^ ty) & 31) * 4]);
                    float a0 = acc[r][0], a1 = acc[r][1], a2 = acc[r][2], a3 = acc[r][3];
                    a0 = fmaf(pf.x, v0.x, a0); a1 = fmaf(pf.x, v0.y, a1);
                    a2 = fmaf(pf.x, v0.z, a2); a3 = fmaf(pf.x, v0.w, a3);
                    a0 = fmaf(pf.y, v1.x, a0); a1 = fmaf(pf.y, v1.y, a1);
                    a2 = fmaf(pf.y, v1.z, a2); a3 = fmaf(pf.y, v1.w, a3);
                    a0 = fmaf(pf.z, v2.x, a0); a1 = fmaf(pf.z, v2.y, a1);
                    a2 = fmaf(pf.z, v2.z, a2); a3 = fmaf(pf.z, v2.w, a3);
                    a0 = fmaf(pf.w, v3.x, a0); a1 = fmaf(pf.w, v3.y, a1);
                    a2 = fmaf(pf.w, v3.z, a2); a3 = fmaf(pf.w, v3.w, a3);
                    acc[r][0] = a0; acc[r][1] = a1; acc[r][2] = a2; acc[r][3] = a3;
                }
            }
        }

        // ---- phase epilogue ----
        #pragma unroll
        for (int r = 0; r < 8; r++) {
            const float inv = 1.f / l[r];
            float4 o;
            o.x = acc[r][0] * inv; o.y = acc[r][1] * inv;
            o.z = acc[r][2] * inv; o.w = acc[r][3] * inv;
            float4* op = reinterpret_cast<float4*>(outp + (size_t)r * Dn);
            if (phase == 0) {
                *op = o;
            } else {
                float4 prev = *op;                 // written by this same thread in phase 0
                o.x += prev.x; o.y += prev.y; o.z += prev.z; o.w += prev.w;
                *op = o;
            }
        }
    }
}

extern "C" void kernel_launch(void* const* d_in, const int* in_sizes, int n_in,
                              void* d_out, int out_size) {
    const float* q = (const float*)d_in[0];
    const float* k = (const float*)d_in[1];
    const float* v = (const float*)d_in[2];
    float* o = (float*)d_out;

    const size_t smem_bytes =
        (size_t)(3 * BQ * ST + BQ * PST) * sizeof(float);   // 176,128 B
    cudaFuncSetAttribute(attn_fwbw2,
                         cudaFuncAttributeMaxDynamicSharedMemorySize,
                         (int)smem_bytes);

    dim3 grid(Ln / BQ, Bn);   // 16 x 8 = 128 CTAs = one full wave
    attn_fwbw2<<<grid, NTH, smem_bytes>>>(q, k, v, o);
}

// round 6
// speedup vs baseline: 3.8684x; 1.8571x over previous
#include <cuda_runtime.h>
#include <cuda_bf16.h>
#include <stdint.h>

#define Bn 8
#define Ln 2048
#define Dn 64
#define BT 128
#define NT 16
#define NTH 256
#define TILE_ELEMS (BT * Dn)          // 8192
#define TILE_BYTES (TILE_ELEMS * 2)   // 16384

// hi/lo bf16 split scratch: [0]=Q(prescaled), [1]=K, [2]=V; SW128-swizzled tile blobs
__device__ __align__(256) __nv_bfloat16 g_hi[3][Bn * Ln * Dn];
__device__ __align__(256) __nv_bfloat16 g_lo[3][Bn * Ln * Dn];

__host__ __device__ __forceinline__ uint32_t sw128(uint32_t x) {
    return x ^ ((x >> 3) & 0x70);
}

// ---------------- smem layout (bytes) ----------------
#define SM_QHI 0
#define SM_QLO TILE_BYTES
#define SM_KV (2 * TILE_BYTES)                 // 2 bufs x {Khi,Klo,Vhi,Vlo}
#define KVBUF(i) (SM_KV + (uint32_t)(i) * 4u * TILE_BYTES)
#define SM_OBUF (SM_KV + 8 * TILE_BYTES)       // 163840: 128*64 floats = 32768 B
#define SM_LBUF (SM_OBUF + 32768)              // 196608: 4*2*32 floats = 1024 B
#define SMEM_TOTAL (SM_LBUF + 1024)            // 197632

// ---------------- asm helpers (base ISA, compute_103-safe) ----------------
__device__ __forceinline__ uint32_t smem_u32(const void* p) {
    uint32_t a;
    asm("{ .reg .u64 t; cvta.to.shared.u64 t, %1; cvt.u32.u64 %0, t; }" : "=r"(a) : "l"(p));
    return a;
}
#define CP16(dst, src) \
    asm volatile("cp.async.cg.shared.global [%0], [%1], 16;" :: "r"(dst), "l"(src))
#define CPCOMMIT() asm volatile("cp.async.commit_group;" ::: "memory")
#define CPWAIT1()  asm volatile("cp.async.wait_group 1;" ::: "memory")
#define CPWAIT0()  asm volatile("cp.async.wait_group 0;" ::: "memory")

__device__ __forceinline__ void ldsm4(uint32_t* r, uint32_t a) {
    asm volatile("ldmatrix.sync.aligned.m8n8.x4.shared.b16 {%0,%1,%2,%3}, [%4];"
                 : "=r"(r[0]), "=r"(r[1]), "=r"(r[2]), "=r"(r[3]) : "r"(a));
}
__device__ __forceinline__ void ldsm4t(uint32_t* r, uint32_t a) {
    asm volatile("ldmatrix.sync.aligned.m8n8.x4.trans.shared.b16 {%0,%1,%2,%3}, [%4];"
                 : "=r"(r[0]), "=r"(r[1]), "=r"(r[2]), "=r"(r[3]) : "r"(a));
}
__device__ __forceinline__ void mma16816(float* c, const uint32_t* a, const uint32_t* b) {
    asm volatile("mma.sync.aligned.m16n8k16.row.col.f32.bf16.bf16.f32 "
                 "{%0,%1,%2,%3}, {%4,%5,%6,%7}, {%8,%9}, {%0,%1,%2,%3};"
                 : "+f"(c[0]), "+f"(c[1]), "+f"(c[2]), "+f"(c[3])
                 : "r"(a[0]), "r"(a[1]), "r"(a[2]), "r"(a[3]), "r"(b[0]), "r"(b[1]));
}

// swizzled address of (row, 16B-chunk) in a 128x64 bf16 tile blob
__device__ __forceinline__ uint32_t taddr(uint32_t base, int row, int ch) {
    return base + ((uint32_t)row << 7) + (uint32_t)((ch ^ (row & 7)) << 4);
}
// pattern P1 (A-frag / V trans-frag): groups {r0,c0},{r0+8,c0},{r0,c0+1},{r0+8,c0+1}
__device__ __forceinline__ uint32_t addrP1(uint32_t base, int r0, int c0, int lane) {
    int grp = lane >> 3;
    return taddr(base, r0 + (grp & 1) * 8 + (lane & 7), c0 + (grp >> 1));
}
// pattern P2 (K B-frag): groups {r0,c0},{r0,c0+1},{r0+8,c0},{r0+8,c0+1}
__device__ __forceinline__ uint32_t addrP2(uint32_t base, int r0, int c0, int lane) {
    int grp = lane >> 3;
    return taddr(base, r0 + (grp >> 1) * 8 + (lane & 7), c0 + (grp & 1));
}

__device__ __forceinline__ uint32_t pk2(__nv_bfloat16 lo, __nv_bfloat16 hi) {
    return (uint32_t)__bfloat16_as_ushort(lo) | ((uint32_t)__bfloat16_as_ushort(hi) << 16);
}

// ---------------- prepass: fp32 -> (hi,lo) bf16, swizzled tile blobs ----------------
__global__ void prep_kernel(const float* __restrict__ q, const float* __restrict__ k,
                            const float* __restrict__ v) {
    int t = blockIdx.y;
    const float* src = (t == 0) ? q : (t == 1) ? k : v;
    uint32_t e = blockIdx.x * blockDim.x + threadIdx.x;
    float x = src[e];
    if (t == 0) x *= 0.125f;                    // fold 1/sqrt(64) into Q
    uint32_t d = e & 63;
    uint32_t row = (e >> 6) & (Ln - 1);
    uint32_t b = e >> 17;
    uint32_t tile = row >> 7, r = row & 127;
    uint32_t off = sw128(r * 128 + d * 2) >> 1;
    size_t o = (size_t)(b * NT + tile) * TILE_ELEMS + off;
    __nv_bfloat16 hi = __float2bfloat16(x);
    g_hi[t][o] = hi;
    g_lo[t][o] = __float2bfloat16(x - __bfloat162float(hi));
}

__device__ __forceinline__ void fetch_kv(uint32_t dst, int b, int j, int tid) {
    size_t blob = (size_t)(b * NT + j) * TILE_ELEMS;
    const char* kh = (const char*)(g_hi[1] + blob);
    const char* kl = (const char*)(g_lo[1] + blob);
    const char* vh = (const char*)(g_hi[2] + blob);
    const char* vl = (const char*)(g_lo[2] + blob);
    #pragma unroll
    for (int i = tid; i < TILE_BYTES / 16; i += NTH) {
        uint32_t o = (uint32_t)i * 16;
        CP16(dst + o, kh + o);
        CP16(dst + TILE_BYTES + o, kl + o);
        CP16(dst + 2 * TILE_BYTES + o, vh + o);
        CP16(dst + 3 * TILE_BYTES + o, vl + o);
    }
}

// ---------------- main fused kernel ----------------
__global__ __launch_bounds__(NTH, 1)
void attn_hmma(float* __restrict__ O) {
    extern __shared__ char smem[];
    const uint32_t sb = smem_u32(smem);
    const int tid = threadIdx.x, lane = tid & 31, w = tid >> 5;
    const int b = blockIdx.y, t = blockIdx.x;
    const int wm = w >> 1, wn = w & 1;
    const int g = lane >> 2, tig = lane & 3;
    const int m0 = wm * 32;            // warp's local row base (rows m0..m0+31)
    const int nb = wn * 64;            // warp's key base within tile

    // prologue: Q hi/lo + first tile's KV
    {
        size_t qb = (size_t)(b * NT + t) * TILE_ELEMS;
        const char* qh = (const char*)(g_hi[0] + qb);
        const char* ql = (const char*)(g_lo[0] + qb);
        #pragma unroll
        for (int i = tid; i < TILE_BYTES / 16; i += NTH) {
            uint32_t o = (uint32_t)i * 16;
            CP16(sb + SM_QHI + o, qh + o);
            CP16(sb + SM_QLO + o, ql + o);
        }
        fetch_kv(sb + KVBUF(0), b, t, tid);     // seq[0] = t
        CPCOMMIT();
    }

    float oacc[2][8][4];
    float lsum[2][2];
    #pragma unroll
    for (int h = 0; h < 2; h++) {
        lsum[h][0] = 0.f; lsum[h][1] = 0.f;
        #pragma unroll
        for (int n = 0; n < 8; n++)
            #pragma unroll
            for (int c = 0; c < 4; c++) oacc[h][n][c] = 0.f;
    }

    #pragma unroll 1
    for (int ii = 0; ii <= NT; ii++) {
        const int j = (ii < NT - t) ? (t + ii) : (ii - (NT - t));
        if (ii < NT) {
            const int jn = (ii + 1 < NT - t) ? (t + ii + 1) : (ii + 1 - (NT - t));
            fetch_kv(sb + KVBUF((ii + 1) & 1), b, jn, tid);
            CPCOMMIT();
            CPWAIT1();
        } else {
            CPWAIT0();
        }
        __syncthreads();                       // tile ii KV ready, prev buffer free
        const uint32_t kb = sb + KVBUF(ii & 1);

        // ---- S = Q @ K^T (3-term hi/lo) ----
        float sacc[2][8][4];
        #pragma unroll
        for (int h = 0; h < 2; h++)
            #pragma unroll
            for (int n = 0; n < 8; n++)
                #pragma unroll
                for (int c = 0; c < 4; c++) sacc[h][n][c] = 0.f;

        #pragma unroll
        for (int kk = 0; kk < 4; kk++) {
            uint32_t qf_h[2][4], qf_l[2][4];
            #pragma unroll
            for (int h = 0; h < 2; h++) {
                ldsm4(qf_h[h], addrP1(sb + SM_QHI, m0 + h * 16, 2 * kk, lane));
                ldsm4(qf_l[h], addrP1(sb + SM_QLO, m0 + h * 16, 2 * kk, lane));
            }
            uint32_t kf_h[4][4], kf_l[4][4];
            #pragma unroll
            for (int p = 0; p < 4; p++) {
                ldsm4(kf_h[p], addrP2(kb, nb + p * 16, 2 * kk, lane));
                ldsm4(kf_l[p], addrP2(kb + TILE_BYTES, nb + p * 16, 2 * kk, lane));
            }
            #pragma unroll
            for (int h = 0; h < 2; h++)
                #pragma unroll
                for (int p = 0; p < 4; p++)
                    #pragma unroll
                    for (int s = 0; s < 2; s++) {
                        const int n = p * 2 + s;
                        mma16816(sacc[h][n], qf_h[h], &kf_h[p][s * 2]);
                        mma16816(sacc[h][n], qf_h[h], &kf_l[p][s * 2]);
                        mma16816(sacc[h][n], qf_l[h], &kf_h[p][s * 2]);
                    }
        }

        // ---- mask + exp + pack to bf16 hi/lo (P stays in registers) ----
        const int mdir = (j == t) ? ((ii < NT - t) ? 1 : 2) : 0;   // 1=fw diag, 2=bw diag
        uint32_t ph[2][8][2], pl[2][8][2];
        #pragma unroll
        for (int h = 0; h < 2; h++) {
            const int lr = m0 + h * 16 + g;
            #pragma unroll
            for (int n = 0; n < 8; n++) {
                const int lc = nb + n * 8 + 2 * tig;
                float p0 = sacc[h][n][0], p1 = sacc[h][n][1];
                float p2 = sacc[h][n][2], p3 = sacc[h][n][3];
                bool z0 = false, z1 = false, z2 = false, z3 = false;
                if (mdir == 1) {        // fw: zero strictly-lower (col < row)
                    z0 = lc < lr;     z1 = lc + 1 < lr;
                    z2 = lc < lr + 8; z3 = lc + 1 < lr + 8;
                } else if (mdir == 2) { // bw: zero strictly-upper (col > row)
                    z0 = lc > lr;     z1 = lc + 1 > lr;
                    z2 = lc > lr + 8; z3 = lc + 1 > lr + 8;
                }
                p0 = z0 ? 0.f : __expf(p0);
                p1 = z1 ? 0.f : __expf(p1);
                p2 = z2 ? 0.f : __expf(p2);
                p3 = z3 ? 0.f : __expf(p3);
                lsum[h][0] += p0 + p1;
                lsum[h][1] += p2 + p3;
                __nv_bfloat16 h0 = __float2bfloat16(p0), h1 = __float2bfloat16(p1);
                __nv_bfloat16 h2 = __float2bfloat16(p2), h3 = __float2bfloat16(p3);
                ph[h][n][0] = pk2(h0, h1);
                ph[h][n][1] = pk2(h2, h3);
                pl[h][n][0] = pk2(__float2bfloat16(p0 - __bfloat162float(h0)),
                                  __float2bfloat16(p1 - __bfloat162float(h1)));
                pl[h][n][1] = pk2(__float2bfloat16(p2 - __bfloat162float(h2)),
                                  __float2bfloat16(p3 - __bfloat162float(h3)));
            }
        }

        // ---- O += P @ V (3-term hi/lo), contraction over this warp's 64 keys ----
        #pragma unroll
        for (int k2 = 0; k2 < 4; k2++) {
            uint32_t vf_h[4][4], vf_l[4][4];
            #pragma unroll
            for (int p = 0; p < 4; p++) {
                ldsm4t(vf_h[p], addrP1(kb + 2 * TILE_BYTES, nb + k2 * 16, 2 * p, lane));
                ldsm4t(vf_l[p], addrP1(kb + 3 * TILE_BYTES, nb + k2 * 16, 2 * p, lane));
            }
            #pragma unroll
            for (int h = 0; h < 2; h++) {
                uint32_t ah[4] = {ph[h][2 * k2][0], ph[h][2 * k2][1],
                                  ph[h][2 * k2 + 1][0], ph[h][2 * k2 + 1][1]};
                uint32_t al[4] = {pl[h][2 * k2][0], pl[h][2 * k2][1],
                                  pl[h][2 * k2 + 1][0], pl[h][2 * k2 + 1][1]};
                #pragma unroll
                for (int p = 0; p < 4; p++)
                    #pragma unroll
                    for (int s = 0; s < 2; s++) {
                        const int dn = p * 2 + s;
                        mma16816(oacc[h][dn], ah, &vf_h[p][s * 2]);
                        mma16816(oacc[h][dn], ah, &vf_l[p][s * 2]);
                        mma16816(oacc[h][dn], al, &vf_h[p][s * 2]);
                    }
            }
        }

        // ---- phase epilogue ----
        if (ii == NT - 1 - t || ii == NT) {
            const bool addmode = (ii == NT);
            // reduce l over the 4 lanes of each row-group
            #pragma unroll
            for (int h = 0; h < 2; h++)
                #pragma unroll
                for (int q2 = 0; q2 < 2; q2++) {
                    lsum[h][q2] += __shfl_xor_sync(0xffffffffu, lsum[h][q2], 1);
                    lsum[h][q2] += __shfl_xor_sync(0xffffffffu, lsum[h][q2], 2);
                }
            float* lbuf = (float*)(smem + SM_LBUF);
            if (tig == 0) {
                #pragma unroll
                for (int h = 0; h < 2; h++) {
                    lbuf[(wm * 2 + wn) * 32 + h * 16 + g] = lsum[h][0];
                    lbuf[(wm * 2 + wn) * 32 + h * 16 + g + 8] = lsum[h][1];
                }
            }
            float* obuf = (float*)(smem + SM_OBUF);
            __syncthreads();
            if (wn == 1) {      // n-half 1 dumps its partial O
                #pragma unroll
                for (int h = 0; h < 2; h++)
                    #pragma unroll
                    for (int n = 0; n < 8; n++) {
                        const int d = n * 8 + 2 * tig;
                        float2* o0 = (float2*)&obuf[(m0 + h * 16 + g) * 64 + d];
                        float2* o1 = (float2*)&obuf[(m0 + h * 16 + g + 8) * 64 + d];
                        *o0 = make_float2(oacc[h][n][0], oacc[h][n][1]);
                        *o1 = make_float2(oacc[h][n][2], oacc[h][n][3]);
                    }
            }
            __syncthreads();
            if (wn == 0) {      // n-half 0 combines, normalizes, writes gmem
                #pragma unroll
                for (int h = 0; h < 2; h++) {
                    const int rr0 = m0 + h * 16 + g, rr1 = rr0 + 8;
                    const float inv0 = 1.f / (lbuf[wm * 64 + rr0 - m0] + lbuf[wm * 64 + 32 + rr0 - m0]);
                    const float inv1 = 1.f / (lbuf[wm * 64 + rr1 - m0] + lbuf[wm * 64 + 32 + rr1 - m0]);
                    #pragma unroll
                    for (int n = 0; n < 8; n++) {
                        const int d = n * 8 + 2 * tig;
                        float2 e0 = *(float2*)&obuf[rr0 * 64 + d];
                        float2 e1 = *(float2*)&obuf[rr1 * 64 + d];
                        float r0 = (oacc[h][n][0] + e0.x) * inv0;
                        float r1 = (oacc[h][n][1] + e0.y) * inv0;
                        float r2 = (oacc[h][n][2] + e1.x) * inv1;
                        float r3 = (oacc[h][n][3] + e1.y) * inv1;
                        float2* g0 = (float2*)(O + ((size_t)b * Ln + t * BT + rr0) * Dn + d);
                        float2* g1 = (float2*)(O + ((size_t)b * Ln + t * BT + rr1) * Dn + d);
                        if (addmode) {
                            float2 q0 = *g0, q1 = *g1;
                            *g0 = make_float2(q0.x + r0, q0.y + r1);
                            *g1 = make_float2(q1.x + r2, q1.y + r3);
                        } else {
                            *g0 = make_float2(r0, r1);
                            *g1 = make_float2(r2, r3);
                        }
                    }
                }
            }
            if (!addmode) {     // reset accumulators for phase 1
                #pragma unroll
                for (int h = 0; h < 2; h++) {
                    lsum[h][0] = 0.f; lsum[h][1] = 0.f;
                    #pragma unroll
                    for (int n = 0; n < 8; n++)
                        #pragma unroll
                        for (int c = 0; c < 4; c++) oacc[h][n][c] = 0.f;
                }
            }
        }
        __syncthreads();        // all reads of buf[ii&1] done before it is refilled
    }
}

extern "C" void kernel_launch(void* const* d_in, const int* in_sizes, int n_in,
                              void* d_out, int out_size) {
    const float* q = (const float*)d_in[0];
    const float* k = (const float*)d_in[1];
    const float* v = (const float*)d_in[2];
    float* o = (float*)d_out;

    dim3 pg((Bn * Ln * Dn) / 256, 3);
    prep_kernel<<<pg, 256>>>(q, k, v);

    cudaFuncSetAttribute(attn_hmma,
                         cudaFuncAttributeMaxDynamicSharedMemorySize, SMEM_TOTAL);
    dim3 grid(NT, Bn);
    attn_hmma<<<grid, NTH, SMEM_TOTAL>>>(o);
}

// round 7
// speedup vs baseline: 6.8800x; 1.7785x over previous
#include <cuda_runtime.h>
#include <cuda_fp16.h>
#include <stdint.h>

#define Bn 8
#define Ln 2048
#define Dn 64
#define BT 128
#define NT 16
#define NTH 256
#define TILE_ELEMS (BT * Dn)          // 8192
#define TILE_BYTES (TILE_ELEMS * 2)   // 16384

// fp16 scratch: [0]=Q(prescaled), [1]=K, [2]=V; SW128-swizzled 128x64 tile blobs
__device__ __align__(256) __half g_h[3][Bn * Ln * Dn];

__host__ __device__ __forceinline__ uint32_t sw128(uint32_t x) {
    return x ^ ((x >> 3) & 0x70);
}

// ---------------- smem layout (bytes) ----------------
#define SM_QH 0
#define SM_KV TILE_BYTES                        // 2 bufs x {Kh, Vh}
#define KVBUF(i) (SM_KV + (uint32_t)(i) * 2u * TILE_BYTES)
#define SM_OBUF (SM_KV + 4 * TILE_BYTES)        // 81920: 128*64 floats = 32768 B
#define SM_LBUF (SM_OBUF + 32768)               // 114688: 8*32 floats
#define SMEM_TOTAL (SM_LBUF + 1024)             // 115712

// ---------------- asm helpers (base ISA, compute_103-safe) ----------------
__device__ __forceinline__ uint32_t smem_u32(const void* p) {
    uint32_t a;
    asm("{ .reg .u64 t; cvta.to.shared.u64 t, %1; cvt.u32.u64 %0, t; }" : "=r"(a) : "l"(p));
    return a;
}
#define CP16(dst, src) \
    asm volatile("cp.async.cg.shared.global [%0], [%1], 16;" :: "r"(dst), "l"(src))
#define CPCOMMIT() asm volatile("cp.async.commit_group;" ::: "memory")
#define CPWAIT1()  asm volatile("cp.async.wait_group 1;" ::: "memory")
#define CPWAIT0()  asm volatile("cp.async.wait_group 0;" ::: "memory")

__device__ __forceinline__ void ldsm4(uint32_t* r, uint32_t a) {
    asm volatile("ldmatrix.sync.aligned.m8n8.x4.shared.b16 {%0,%1,%2,%3}, [%4];"
                 : "=r"(r[0]), "=r"(r[1]), "=r"(r[2]), "=r"(r[3]) : "r"(a));
}
__device__ __forceinline__ void ldsm4t(uint32_t* r, uint32_t a) {
    asm volatile("ldmatrix.sync.aligned.m8n8.x4.trans.shared.b16 {%0,%1,%2,%3}, [%4];"
                 : "=r"(r[0]), "=r"(r[1]), "=r"(r[2]), "=r"(r[3]) : "r"(a));
}
__device__ __forceinline__ void mma16816(float* c, const uint32_t* a, const uint32_t* b) {
    asm volatile("mma.sync.aligned.m16n8k16.row.col.f32.f16.f16.f32 "
                 "{%0,%1,%2,%3}, {%4,%5,%6,%7}, {%8,%9}, {%0,%1,%2,%3};"
                 : "+f"(c[0]), "+f"(c[1]), "+f"(c[2]), "+f"(c[3])
                 : "r"(a[0]), "r"(a[1]), "r"(a[2]), "r"(a[3]), "r"(b[0]), "r"(b[1]));
}

// swizzled address of (row, 16B-chunk) in a 128x64 fp16 tile blob
__device__ __forceinline__ uint32_t taddr(uint32_t base, int row, int ch) {
    return base + ((uint32_t)row << 7) + (uint32_t)((ch ^ (row & 7)) << 4);
}
// pattern P1 (A-frag / V trans-frag): groups {r0,c0},{r0+8,c0},{r0,c0+1},{r0+8,c0+1}
__device__ __forceinline__ uint32_t addrP1(uint32_t base, int r0, int c0, int lane) {
    int grp = lane >> 3;
    return taddr(base, r0 + (grp & 1) * 8 + (lane & 7), c0 + (grp >> 1));
}
// pattern P2 (K B-frag): groups {r0,c0},{r0,c0+1},{r0+8,c0},{r0+8,c0+1}
__device__ __forceinline__ uint32_t addrP2(uint32_t base, int r0, int c0, int lane) {
    int grp = lane >> 3;
    return taddr(base, r0 + (grp >> 1) * 8 + (lane & 7), c0 + (grp & 1));
}

__device__ __forceinline__ uint32_t pkh2(float lo, float hi) {
    __half2 h = __floats2half2_rn(lo, hi);
    return *reinterpret_cast<uint32_t*>(&h);
}

// ---------------- prepass: fp32 -> fp16, swizzled tile blobs ----------------
__global__ void prep_kernel(const float* __restrict__ q, const float* __restrict__ k,
                            const float* __restrict__ v) {
    int t = blockIdx.y;
    const float* src = (t == 0) ? q : (t == 1) ? k : v;
    uint32_t e = blockIdx.x * blockDim.x + threadIdx.x;
    float x = src[e];
    if (t == 0) x *= 0.125f;                    // fold 1/sqrt(64) into Q
    uint32_t d = e & 63;
    uint32_t row = (e >> 6) & (Ln - 1);
    uint32_t b = e >> 17;
    uint32_t tile = row >> 7, r = row & 127;
    uint32_t off = sw128(r * 128 + d * 2) >> 1;
    size_t o = (size_t)(b * NT + tile) * TILE_ELEMS + off;
    g_h[t][o] = __float2half(x);
}

__device__ __forceinline__ void fetch_kv(uint32_t dst, int b, int j, int tid) {
    size_t blob = (size_t)(b * NT + j) * TILE_ELEMS;
    const char* kh = (const char*)(g_h[1] + blob);
    const char* vh = (const char*)(g_h[2] + blob);
    #pragma unroll
    for (int i = tid; i < TILE_BYTES / 16; i += NTH) {
        uint32_t o = (uint32_t)i * 16;
        CP16(dst + o, kh + o);
        CP16(dst + TILE_BYTES + o, vh + o);
    }
}

// ---------------- main fused kernel ----------------
__global__ __launch_bounds__(NTH, 1)
void attn_hmma(float* __restrict__ O) {
    extern __shared__ char smem[];
    const uint32_t sb = smem_u32(smem);
    const int tid = threadIdx.x, lane = tid & 31, w = tid >> 5;
    const int b = blockIdx.y, t = blockIdx.x;
    const int wm = w >> 1, wn = w & 1;
    const int g = lane >> 2, tig = lane & 3;
    const int m0 = wm * 32;            // warp's local row base (rows m0..m0+31)
    const int nb = wn * 64;            // warp's key base within tile

    // prologue: Q + first tile's KV
    {
        size_t qb = (size_t)(b * NT + t) * TILE_ELEMS;
        const char* qh = (const char*)(g_h[0] + qb);
        #pragma unroll
        for (int i = tid; i < TILE_BYTES / 16; i += NTH) {
            uint32_t o = (uint32_t)i * 16;
            CP16(sb + SM_QH + o, qh + o);
        }
        fetch_kv(sb + KVBUF(0), b, t, tid);     // seq[0] = t
        CPCOMMIT();
    }

    float oacc[2][8][4];
    float lsum[2][2];
    #pragma unroll
    for (int h = 0; h < 2; h++) {
        lsum[h][0] = 0.f; lsum[h][1] = 0.f;
        #pragma unroll
        for (int n = 0; n < 8; n++)
            #pragma unroll
            for (int c = 0; c < 4; c++) oacc[h][n][c] = 0.f;
    }

    uint32_t qf[4][2][4];   // Q fragments, resident across all tiles

    #pragma unroll 1
    for (int ii = 0; ii <= NT; ii++) {
        const int j = (ii < NT - t) ? (t + ii) : (ii - (NT - t));
        if (ii < NT) {
            const int jn = (ii + 1 < NT - t) ? (t + ii + 1) : (ii + 1 - (NT - t));
            fetch_kv(sb + KVBUF((ii + 1) & 1), b, jn, tid);
            CPCOMMIT();
            CPWAIT1();
        } else {
            CPWAIT0();
        }
        __syncthreads();                       // tile ii KV ready, prev buffer free
        const uint32_t kb = sb + KVBUF(ii & 1);

        if (ii == 0) {                         // hoist Q fragments once
            #pragma unroll
            for (int kk = 0; kk < 4; kk++)
                #pragma unroll
                for (int h = 0; h < 2; h++)
                    ldsm4(qf[kk][h], addrP1(sb + SM_QH, m0 + h * 16, 2 * kk, lane));
        }

        // ---- S = Q @ K^T (single fp16) ----
        float sacc[2][8][4];
        #pragma unroll
        for (int h = 0; h < 2; h++)
            #pragma unroll
            for (int n = 0; n < 8; n++)
                #pragma unroll
                for (int c = 0; c < 4; c++) sacc[h][n][c] = 0.f;

        #pragma unroll
        for (int kk = 0; kk < 4; kk++) {
            uint32_t kf[4][4];
            #pragma unroll
            for (int p = 0; p < 4; p++)
                ldsm4(kf[p], addrP2(kb, nb + p * 16, 2 * kk, lane));
            #pragma unroll
            for (int h = 0; h < 2; h++)
                #pragma unroll
                for (int p = 0; p < 4; p++)
                    #pragma unroll
                    for (int s = 0; s < 2; s++)
                        mma16816(sacc[h][p * 2 + s], qf[kk][h], &kf[p][s * 2]);
        }

        // ---- mask + exp + pack to fp16 (P stays in registers) ----
        const int mdir = (j == t) ? ((ii < NT - t) ? 1 : 2) : 0;   // 1=fw diag, 2=bw diag
        uint32_t ph[2][8][2];
        #pragma unroll
        for (int h = 0; h < 2; h++) {
            const int lr = m0 + h * 16 + g;
            #pragma unroll
            for (int n = 0; n < 8; n++) {
                const int lc = nb + n * 8 + 2 * tig;
                float p0 = sacc[h][n][0], p1 = sacc[h][n][1];
                float p2 = sacc[h][n][2], p3 = sacc[h][n][3];
                bool z0 = false, z1 = false, z2 = false, z3 = false;
                if (mdir == 1) {        // fw: zero strictly-lower (col < row)
                    z0 = lc < lr;     z1 = lc + 1 < lr;
                    z2 = lc < lr + 8; z3 = lc + 1 < lr + 8;
                } else if (mdir == 2) { // bw: zero strictly-upper (col > row)
                    z0 = lc > lr;     z1 = lc + 1 > lr;
                    z2 = lc > lr + 8; z3 = lc + 1 > lr + 8;
                }
                p0 = z0 ? 0.f : __expf(p0);
                p1 = z1 ? 0.f : __expf(p1);
                p2 = z2 ? 0.f : __expf(p2);
                p3 = z3 ? 0.f : __expf(p3);
                lsum[h][0] += p0 + p1;
                lsum[h][1] += p2 + p3;
                ph[h][n][0] = pkh2(p0, p1);
                ph[h][n][1] = pkh2(p2, p3);
            }
        }

        // ---- O += P @ V (single fp16), contraction over this warp's 64 keys ----
        #pragma unroll
        for (int k2 = 0; k2 < 4; k2++) {
            uint32_t vf[4][4];
            #pragma unroll
            for (int p = 0; p < 4; p++)
                ldsm4t(vf[p], addrP1(kb + TILE_BYTES, nb + k2 * 16, 2 * p, lane));
            #pragma unroll
            for (int h = 0; h < 2; h++) {
                uint32_t ah[4] = {ph[h][2 * k2][0], ph[h][2 * k2][1],
                                  ph[h][2 * k2 + 1][0], ph[h][2 * k2 + 1][1]};
                #pragma unroll
                for (int p = 0; p < 4; p++)
                    #pragma unroll
                    for (int s = 0; s < 2; s++)
                        mma16816(oacc[h][p * 2 + s], ah, &vf[p][s * 2]);
            }
        }

        // ---- phase epilogue ----
        if (ii == NT - 1 - t || ii == NT) {
            const bool addmode = (ii == NT);
            #pragma unroll
            for (int h = 0; h < 2; h++)
                #pragma unroll
                for (int q2 = 0; q2 < 2; q2++) {
                    lsum[h][q2] += __shfl_xor_sync(0xffffffffu, lsum[h][q2], 1);
                    lsum[h][q2] += __shfl_xor_sync(0xffffffffu, lsum[h][q2], 2);
                }
            float* lbuf = (float*)(smem + SM_LBUF);
            if (tig == 0) {
                #pragma unroll
                for (int h = 0; h < 2; h++) {
                    lbuf[(wm * 2 + wn) * 32 + h * 16 + g] = lsum[h][0];
                    lbuf[(wm * 2 + wn) * 32 + h * 16 + g + 8] = lsum[h][1];
                }
            }
            float* obuf = (float*)(smem + SM_OBUF);
            __syncthreads();
            if (wn == 1) {      // n-half 1 dumps its partial O
                #pragma unroll
                for (int h = 0; h < 2; h++)
                    #pragma unroll
                    for (int n = 0; n < 8; n++) {
                        const int d = n * 8 + 2 * tig;
                        float2* o0 = (float2*)&obuf[(m0 + h * 16 + g) * 64 + d];
                        float2* o1 = (float2*)&obuf[(m0 + h * 16 + g + 8) * 64 + d];
                        *o0 = make_float2(oacc[h][n][0], oacc[h][n][1]);
                        *o1 = make_float2(oacc[h][n][2], oacc[h][n][3]);
                    }
            }
            __syncthreads();
            if (wn == 0) {      // n-half 0 combines, normalizes, writes gmem
                #pragma unroll
                for (int h = 0; h < 2; h++) {
                    const int rr0 = m0 + h * 16 + g, rr1 = rr0 + 8;
                    const float inv0 = 1.f / (lbuf[wm * 64 + rr0 - m0] + lbuf[wm * 64 + 32 + rr0 - m0]);
                    const float inv1 = 1.f / (lbuf[wm * 64 + rr1 - m0] + lbuf[wm * 64 + 32 + rr1 - m0]);
                    #pragma unroll
                    for (int n = 0; n < 8; n++) {
                        const int d = n * 8 + 2 * tig;
                        float2 e0 = *(float2*)&obuf[rr0 * 64 + d];
                        float2 e1 = *(float2*)&obuf[rr1 * 64 + d];
                        float r0 = (oacc[h][n][0] + e0.x) * inv0;
                        float r1 = (oacc[h][n][1] + e0.y) * inv0;
                        float r2 = (oacc[h][n][2] + e1.x) * inv1;
                        float r3 = (oacc[h][n][3] + e1.y) * inv1;
                        float2* g0 = (float2*)(O + ((size_t)b * Ln + t * BT + rr0) * Dn + d);
                        float2* g1 = (float2*)(O + ((size_t)b * Ln + t * BT + rr1) * Dn + d);
                        if (addmode) {
                            float2 q0 = *g0, q1 = *g1;
                            *g0 = make_float2(q0.x + r0, q0.y + r1);
                            *g1 = make_float2(q1.x + r2, q1.y + r3);
                        } else {
                            *g0 = make_float2(r0, r1);
                            *g1 = make_float2(r2, r3);
                        }
                    }
                }
            }
            if (!addmode) {     // reset accumulators for phase 1
                #pragma unroll
                for (int h = 0; h < 2; h++) {
                    lsum[h][0] = 0.f; lsum[h][1] = 0.f;
                    #pragma unroll
                    for (int n = 0; n < 8; n++)
                        #pragma unroll
                        for (int c = 0; c < 4; c++) oacc[h][n][c] = 0.f;
                }
            }
        }
        __syncthreads();        // all reads of buf[ii&1] done before it is refilled
    }
}

extern "C" void kernel_launch(void* const* d_in, const int* in_sizes, int n_in,
                              void* d_out, int out_size) {
    const float* q = (const float*)d_in[0];
    const float* k = (const float*)d_in[1];
    const float* v = (const float*)d_in[2];
    float* o = (float*)d_out;

    dim3 pg((Bn * Ln * Dn) / 256, 3);
    prep_kernel<<<pg, 256>>>(q, k, v);

    cudaFuncSetAttribute(attn_hmma,
                         cudaFuncAttributeMaxDynamicSharedMemorySize, SMEM_TOTAL);
    dim3 grid(NT, Bn);
    attn_hmma<<<grid, NTH, SMEM_TOTAL>>>(o);
}

// round 8
// speedup vs baseline: 8.6145x; 1.2521x over previous
#include <cuda_runtime.h>
#include <cuda_fp16.h>
#include <stdint.h>

#define Bn 8
#define Ln 2048
#define Dn 64
#define BT 128
#define NT 16
#define NTH 512
#define TILE_ELEMS (BT * Dn)          // 8192
#define TILE_BYTES (TILE_ELEMS * 2)   // 16384

// fp16 scratch: [0]=Q(prescaled by 0.125*log2e), [1]=K, [2]=V; SW128-swizzled tile blobs
__device__ __align__(256) __half g_h[3][Bn * Ln * Dn];

__host__ __device__ __forceinline__ uint32_t sw128(uint32_t x) {
    return x ^ ((x >> 3) & 0x70);
}

// ---------------- smem layout (bytes) ----------------
#define SM_QH 0
#define SM_KV TILE_BYTES                        // 2 bufs x {Kh, Vh}
#define KVBUF(i) (SM_KV + (uint32_t)(i) * 2u * TILE_BYTES)
#define SM_OBUF (SM_KV + 4 * TILE_BYTES)        // 81920: 128*64 floats = 32768 B
#define SM_LBUF (SM_OBUF + 32768)               // 114688: 2*128 floats
#define SMEM_TOTAL (SM_LBUF + 1024)             // 115712

// ---------------- asm helpers (base ISA, compute_103-safe) ----------------
__device__ __forceinline__ uint32_t smem_u32(const void* p) {
    uint32_t a;
    asm("{ .reg .u64 t; cvta.to.shared.u64 t, %1; cvt.u32.u64 %0, t; }" : "=r"(a) : "l"(p));
    return a;
}
#define CP16(dst, src) \
    asm volatile("cp.async.cg.shared.global [%0], [%1], 16;" :: "r"(dst), "l"(src))
#define CPCOMMIT() asm volatile("cp.async.commit_group;" ::: "memory")
#define CPWAIT1()  asm volatile("cp.async.wait_group 1;" ::: "memory")
#define CPWAIT0()  asm volatile("cp.async.wait_group 0;" ::: "memory")

__device__ __forceinline__ void ldsm4(uint32_t* r, uint32_t a) {
    asm volatile("ldmatrix.sync.aligned.m8n8.x4.shared.b16 {%0,%1,%2,%3}, [%4];"
                 : "=r"(r[0]), "=r"(r[1]), "=r"(r[2]), "=r"(r[3]) : "r"(a));
}
__device__ __forceinline__ void ldsm4t(uint32_t* r, uint32_t a) {
    asm volatile("ldmatrix.sync.aligned.m8n8.x4.trans.shared.b16 {%0,%1,%2,%3}, [%4];"
                 : "=r"(r[0]), "=r"(r[1]), "=r"(r[2]), "=r"(r[3]) : "r"(a));
}
__device__ __forceinline__ void mma16816(float* c, const uint32_t* a, const uint32_t* b) {
    asm volatile("mma.sync.aligned.m16n8k16.row.col.f32.f16.f16.f32 "
                 "{%0,%1,%2,%3}, {%4,%5,%6,%7}, {%8,%9}, {%0,%1,%2,%3};"
                 : "+f"(c[0]), "+f"(c[1]), "+f"(c[2]), "+f"(c[3])
                 : "r"(a[0]), "r"(a[1]), "r"(a[2]), "r"(a[3]), "r"(b[0]), "r"(b[1]));
}

// swizzled address of (row, 16B-chunk) in a 128x64 fp16 tile blob
__device__ __forceinline__ uint32_t taddr(uint32_t base, int row, int ch) {
    return base + ((uint32_t)row << 7) + (uint32_t)((ch ^ (row & 7)) << 4);
}
// pattern P1 (A-frag / V trans-frag): groups {r0,c0},{r0+8,c0},{r0,c0+1},{r0+8,c0+1}
__device__ __forceinline__ uint32_t addrP1(uint32_t base, int r0, int c0, int lane) {
    int grp = lane >> 3;
    return taddr(base, r0 + (grp & 1) * 8 + (lane & 7), c0 + (grp >> 1));
}
// pattern P2 (K B-frag): groups {r0,c0},{r0,c0+1},{r0+8,c0},{r0+8,c0+1}
__device__ __forceinline__ uint32_t addrP2(uint32_t base, int r0, int c0, int lane) {
    int grp = lane >> 3;
    return taddr(base, r0 + (grp >> 1) * 8 + (lane & 7), c0 + (grp & 1));
}

__device__ __forceinline__ uint32_t pkh2(float lo, float hi) {
    __half2 h = __floats2half2_rn(lo, hi);
    return *reinterpret_cast<uint32_t*>(&h);
}

// ---------------- prepass: fp32 -> fp16, swizzled tile blobs ----------------
__global__ void prep_kernel(const float* __restrict__ q, const float* __restrict__ k,
                            const float* __restrict__ v) {
    int t = blockIdx.y;
    const float* src = (t == 0) ? q : (t == 1) ? k : v;
    uint32_t e = blockIdx.x * blockDim.x + threadIdx.x;
    float x = src[e];
    if (t == 0) x *= 0.125f * 1.44269504088896f;   // fold 1/sqrt(64) and log2(e) into Q
    uint32_t d = e & 63;
    uint32_t row = (e >> 6) & (Ln - 1);
    uint32_t b = e >> 17;
    uint32_t tile = row >> 7, r = row & 127;
    uint32_t off = sw128(r * 128 + d * 2) >> 1;
    size_t o = (size_t)(b * NT + tile) * TILE_ELEMS + off;
    g_h[t][o] = __float2half(x);
}

__device__ __forceinline__ void fetch_kv(uint32_t dst, int b, int j, int tid) {
    size_t blob = (size_t)(b * NT + j) * TILE_ELEMS;
    const char* kh = (const char*)(g_h[1] + blob);
    const char* vh = (const char*)(g_h[2] + blob);
    #pragma unroll
    for (int i = tid; i < TILE_BYTES / 16; i += NTH) {
        uint32_t o = (uint32_t)i * 16;
        CP16(dst + o, kh + o);
        CP16(dst + TILE_BYTES + o, vh + o);
    }
}

// ---------------- main fused kernel ----------------
__global__ __launch_bounds__(NTH, 1)
void attn_hmma(float* __restrict__ O) {
    extern __shared__ char smem[];
    const uint32_t sb = smem_u32(smem);
    const int tid = threadIdx.x, lane = tid & 31, w = tid >> 5;
    const int b = blockIdx.y, t = blockIdx.x;
    const int wm = w >> 1, wn = w & 1;          // wm 0..7, wn 0..1
    const int g = lane >> 2, tig = lane & 3;
    const int m0 = wm * 16;            // warp's local row base (rows m0..m0+15)
    const int nb = wn * 64;            // warp's key base within tile
    const uint32_t ones2[2] = {0x3C003C00u, 0x3C003C00u};   // fp16 {1,1}

    // prologue: Q + first tile's KV
    {
        size_t qb = (size_t)(b * NT + t) * TILE_ELEMS;
        const char* qh = (const char*)(g_h[0] + qb);
        #pragma unroll
        for (int i = tid; i < TILE_BYTES / 16; i += NTH) {
            uint32_t o = (uint32_t)i * 16;
            CP16(sb + SM_QH + o, qh + o);
        }
        fetch_kv(sb + KVBUF(0), b, t, tid);     // seq[0] = t
        CPCOMMIT();
    }

    float oacc[8][4];
    float lacc[4];
    #pragma unroll
    for (int n = 0; n < 8; n++)
        #pragma unroll
        for (int c = 0; c < 4; c++) oacc[n][c] = 0.f;
    #pragma unroll
    for (int c = 0; c < 4; c++) lacc[c] = 0.f;

    #pragma unroll 1
    for (int ii = 0; ii <= NT; ii++) {
        const int j = (ii < NT - t) ? (t + ii) : (ii - (NT - t));
        if (ii < NT) {
            const int jn = (ii + 1 < NT - t) ? (t + ii + 1) : (ii + 1 - (NT - t));
            fetch_kv(sb + KVBUF((ii + 1) & 1), b, jn, tid);
            CPCOMMIT();
            CPWAIT1();
        } else {
            CPWAIT0();
        }
        __syncthreads();                       // tile ii KV ready, prev buffer free
        const uint32_t kb = sb + KVBUF(ii & 1);

        // ---- S = Q @ K^T (single fp16) ----
        float sacc[8][4];
        #pragma unroll
        for (int n = 0; n < 8; n++)
            #pragma unroll
            for (int c = 0; c < 4; c++) sacc[n][c] = 0.f;

        #pragma unroll
        for (int kk = 0; kk < 4; kk++) {
            uint32_t qfr[4];
            ldsm4(qfr, addrP1(sb + SM_QH, m0, 2 * kk, lane));
            uint32_t kf[4][4];
            #pragma unroll
            for (int p = 0; p < 4; p++)
                ldsm4(kf[p], addrP2(kb, nb + p * 16, 2 * kk, lane));
            #pragma unroll
            for (int p = 0; p < 4; p++)
                #pragma unroll
                for (int s = 0; s < 2; s++)
                    mma16816(sacc[p * 2 + s], qfr, &kf[p][s * 2]);
        }

        // ---- mask + exp2 + pack to fp16 (P stays in registers) ----
        const int mdir = (j == t) ? ((ii < NT - t) ? 1 : 2) : 0;   // 1=fw diag, 2=bw diag
        uint32_t ph[8][2];
        {
            const int lr = m0 + g;
            #pragma unroll
            for (int n = 0; n < 8; n++) {
                const int lc = nb + n * 8 + 2 * tig;
                float p0 = sacc[n][0], p1 = sacc[n][1];
                float p2 = sacc[n][2], p3 = sacc[n][3];
                bool z0 = false, z1 = false, z2 = false, z3 = false;
                if (mdir == 1) {        // fw: zero strictly-lower (col < row)
                    z0 = lc < lr;     z1 = lc + 1 < lr;
                    z2 = lc < lr + 8; z3 = lc + 1 < lr + 8;
                } else if (mdir == 2) { // bw: zero strictly-upper (col > row)
                    z0 = lc > lr;     z1 = lc + 1 > lr;
                    z2 = lc > lr + 8; z3 = lc + 1 > lr + 8;
                }
                p0 = z0 ? 0.f : exp2f(p0);
                p1 = z1 ? 0.f : exp2f(p1);
                p2 = z2 ? 0.f : exp2f(p2);
                p3 = z3 ? 0.f : exp2f(p3);
                ph[n][0] = pkh2(p0, p1);
                ph[n][1] = pkh2(p2, p3);
            }
        }

        // ---- O += P @ V and l += P @ 1 (ones-MMA, no shuffles) ----
        #pragma unroll
        for (int k2 = 0; k2 < 4; k2++) {
            uint32_t vf[4][4];
            #pragma unroll
            for (int p = 0; p < 4; p++)
                ldsm4t(vf[p], addrP1(kb + TILE_BYTES, nb + k2 * 16, 2 * p, lane));
            uint32_t ah[4] = {ph[2 * k2][0], ph[2 * k2][1],
                              ph[2 * k2 + 1][0], ph[2 * k2 + 1][1]};
            #pragma unroll
            for (int p = 0; p < 4; p++)
                #pragma unroll
                for (int s = 0; s < 2; s++)
                    mma16816(oacc[p * 2 + s], ah, &vf[p][s * 2]);
            mma16816(lacc, ah, ones2);       // row sums: lacc[0]=row g, lacc[2]=row g+8
        }

        // ---- phase epilogue ----
        if (ii == NT - 1 - t || ii == NT) {
            const bool addmode = (ii == NT);
            float* lbuf = (float*)(smem + SM_LBUF);
            if (tig == 0) {
                lbuf[wn * 128 + m0 + g] = lacc[0];
                lbuf[wn * 128 + m0 + g + 8] = lacc[2];
            }
            float* obuf = (float*)(smem + SM_OBUF);
            __syncthreads();
            if (wn == 1) {      // n-half 1 dumps its partial O
                #pragma unroll
                for (int n = 0; n < 8; n++) {
                    const int d = n * 8 + 2 * tig;
                    *(float2*)&obuf[(m0 + g) * 64 + d]     = make_float2(oacc[n][0], oacc[n][1]);
                    *(float2*)&obuf[(m0 + g + 8) * 64 + d] = make_float2(oacc[n][2], oacc[n][3]);
                }
            }
            __syncthreads();
            if (wn == 0) {      // n-half 0 combines, normalizes, writes gmem
                const int rr0 = m0 + g, rr1 = rr0 + 8;
                const float inv0 = 1.f / (lbuf[rr0] + lbuf[128 + rr0]);
                const float inv1 = 1.f / (lbuf[rr1] + lbuf[128 + rr1]);
                #pragma unroll
                for (int n = 0; n < 8; n++) {
                    const int d = n * 8 + 2 * tig;
                    float2 e0 = *(float2*)&obuf[rr0 * 64 + d];
                    float2 e1 = *(float2*)&obuf[rr1 * 64 + d];
                    float r0 = (oacc[n][0] + e0.x) * inv0;
                    float r1 = (oacc[n][1] + e0.y) * inv0;
                    float r2 = (oacc[n][2] + e1.x) * inv1;
                    float r3 = (oacc[n][3] + e1.y) * inv1;
                    float2* g0 = (float2*)(O + ((size_t)b * Ln + t * BT + rr0) * Dn + d);
                    float2* g1 = (float2*)(O + ((size_t)b * Ln + t * BT + rr1) * Dn + d);
                    if (addmode) {
                        float2 q0 = *g0, q1 = *g1;
                        *g0 = make_float2(q0.x + r0, q0.y + r1);
                        *g1 = make_float2(q1.x + r2, q1.y + r3);
                    } else {
                        *g0 = make_float2(r0, r1);
                        *g1 = make_float2(r2, r3);
                    }
                }
            }
            if (!addmode) {     // reset accumulators for phase 1
                #pragma unroll
                for (int n = 0; n < 8; n++)
                    #pragma unroll
                    for (int c = 0; c < 4; c++) oacc[n][c] = 0.f;
                #pragma unroll
                for (int c = 0; c < 4; c++) lacc[c] = 0.f;
            }
        }
        __syncthreads();        // all reads of buf[ii&1] done before it is refilled
    }
}

extern "C" void kernel_launch(void* const* d_in, const int* in_sizes, int n_in,
                              void* d_out, int out_size) {
    const float* q = (const float*)d_in[0];
    const float* k = (const float*)d_in[1];
    const float* v = (const float*)d_in[2];
    float* o = (float*)d_out;

    dim3 pg((Bn * Ln * Dn) / 256, 3);
    prep_kernel<<<pg, 256>>>(q, k, v);

    cudaFuncSetAttribute(attn_hmma,
                         cudaFuncAttributeMaxDynamicSharedMemorySize, SMEM_TOTAL);
    dim3 grid(NT, Bn);
    attn_hmma<<<grid, NTH, SMEM_TOTAL>>>(o);
}

// round 9
// speedup vs baseline: 11.7661x; 1.3659x over previous
#include <cuda_runtime.h>
#include <cuda_fp16.h>
#include <stdint.h>

#define Bn 8
#define Ln 2048
#define Dn 64
#define BT 128
#define NT 16
#define NTH 512
#define TILE_ELEMS (BT * Dn)          // 8192
#define TILE_BYTES (TILE_ELEMS * 2)   // 16384

// fp16 scratch: [0]=Q(prescaled by 0.125*log2e), [1]=K, [2]=V; SW128-swizzled tile blobs
__device__ __align__(256) __half g_h[3][Bn * Ln * Dn];

__host__ __device__ __forceinline__ uint32_t sw128(uint32_t x) {
    return x ^ ((x >> 3) & 0x70);
}

// ---------------- smem layout (bytes) ----------------
#define SM_QH 0
#define SM_KV TILE_BYTES                        // 2 bufs x {Kh, Vh}
#define KVBUF(i) (SM_KV + (uint32_t)(i) * 2u * TILE_BYTES)
#define SM_OBUF (SM_KV + 4 * TILE_BYTES)        // 81920: 128*64 floats = 32768 B
#define SM_LBUF (SM_OBUF + 32768)               // 114688: 2*128 floats
#define SMEM_TOTAL (SM_LBUF + 1024)             // 115712

// ---------------- asm helpers (base ISA, compute_103-safe) ----------------
__device__ __forceinline__ uint32_t smem_u32(const void* p) {
    uint32_t a;
    asm("{ .reg .u64 t; cvta.to.shared.u64 t, %1; cvt.u32.u64 %0, t; }" : "=r"(a) : "l"(p));
    return a;
}
#define CP16(dst, src) \
    asm volatile("cp.async.cg.shared.global [%0], [%1], 16;" :: "r"(dst), "l"(src))
#define CPCOMMIT() asm volatile("cp.async.commit_group;" ::: "memory")
#define CPWAIT1()  asm volatile("cp.async.wait_group 1;" ::: "memory")
#define CPWAIT0()  asm volatile("cp.async.wait_group 0;" ::: "memory")

__device__ __forceinline__ void ldsm4(uint32_t* r, uint32_t a) {
    asm volatile("ldmatrix.sync.aligned.m8n8.x4.shared.b16 {%0,%1,%2,%3}, [%4];"
                 : "=r"(r[0]), "=r"(r[1]), "=r"(r[2]), "=r"(r[3]) : "r"(a));
}
__device__ __forceinline__ void ldsm4t(uint32_t* r, uint32_t a) {
    asm volatile("ldmatrix.sync.aligned.m8n8.x4.trans.shared.b16 {%0,%1,%2,%3}, [%4];"
                 : "=r"(r[0]), "=r"(r[1]), "=r"(r[2]), "=r"(r[3]) : "r"(a));
}
__device__ __forceinline__ void mma16816(float* c, const uint32_t* a, const uint32_t* b) {
    asm volatile("mma.sync.aligned.m16n8k16.row.col.f32.f16.f16.f32 "
                 "{%0,%1,%2,%3}, {%4,%5,%6,%7}, {%8,%9}, {%0,%1,%2,%3};"
                 : "+f"(c[0]), "+f"(c[1]), "+f"(c[2]), "+f"(c[3])
                 : "r"(a[0]), "r"(a[1]), "r"(a[2]), "r"(a[3]), "r"(b[0]), "r"(b[1]));
}
// pack two fp32 to half2 (bits), then exp2 on both halves in one MUFU op
__device__ __forceinline__ uint32_t pkh2(float lo, float hi) {
    __half2 h = __floats2half2_rn(lo, hi);
    return *reinterpret_cast<uint32_t*>(&h);
}
__device__ __forceinline__ uint32_t ex2h2(uint32_t x) {
    uint32_t r;
    asm("ex2.approx.f16x2 %0, %1;" : "=r"(r) : "r"(x));
    return r;
}

// swizzled address of (row, 16B-chunk) in a 128x64 fp16 tile blob
__device__ __forceinline__ uint32_t taddr(uint32_t base, int row, int ch) {
    return base + ((uint32_t)row << 7) + (uint32_t)((ch ^ (row & 7)) << 4);
}
// pattern P1 (A-frag / V trans-frag): groups {r0,c0},{r0+8,c0},{r0,c0+1},{r0+8,c0+1}
__device__ __forceinline__ uint32_t addrP1(uint32_t base, int r0, int c0, int lane) {
    int grp = lane >> 3;
    return taddr(base, r0 + (grp & 1) * 8 + (lane & 7), c0 + (grp >> 1));
}
// pattern P2 (K B-frag): groups {r0,c0},{r0,c0+1},{r0+8,c0},{r0+8,c0+1}
__device__ __forceinline__ uint32_t addrP2(uint32_t base, int r0, int c0, int lane) {
    int grp = lane >> 3;
    return taddr(base, r0 + (grp >> 1) * 8 + (lane & 7), c0 + (grp & 1));
}

// ---------------- prepass: fp32 -> fp16, swizzled tile blobs (8 elems/thread) ----------------
__global__ void prep_kernel(const float* __restrict__ q, const float* __restrict__ k,
                            const float* __restrict__ v) {
    const int t = blockIdx.y;
    const float* src = (t == 0) ? q : (t == 1) ? k : v;
    const float sc = (t == 0) ? (0.125f * 1.44269504088896f) : 1.f;  // fold 1/8 and log2e into Q
    uint32_t i8 = blockIdx.x * blockDim.x + threadIdx.x;   // 16B-chunk index
    uint32_t c   = i8 & 7;                 // d-chunk (8 halves per chunk)
    uint32_t row = (i8 >> 3) & (Ln - 1);
    uint32_t b   = i8 >> 14;
    const float4* s4 = reinterpret_cast<const float4*>(src + ((size_t)(b * Ln + row)) * Dn + c * 8);
    float4 x0 = s4[0], x1 = s4[1];
    uint32_t h0 = pkh2(x0.x * sc, x0.y * sc);
    uint32_t h1 = pkh2(x0.z * sc, x0.w * sc);
    uint32_t h2 = pkh2(x1.x * sc, x1.y * sc);
    uint32_t h3 = pkh2(x1.z * sc, x1.w * sc);
    uint32_t tile = row >> 7, r = row & 127;
    uint32_t off = sw128(r * 128 + c * 16);
    uint4* dst = reinterpret_cast<uint4*>(
        reinterpret_cast<char*>(g_h[t] + (size_t)(b * NT + tile) * TILE_ELEMS) + off);
    *dst = make_uint4(h0, h1, h2, h3);
}

__device__ __forceinline__ void fetch_kv(uint32_t dst, int b, int j, int tid) {
    size_t blob = (size_t)(b * NT + j) * TILE_ELEMS;
    const char* kh = (const char*)(g_h[1] + blob);
    const char* vh = (const char*)(g_h[2] + blob);
    #pragma unroll
    for (int i = tid; i < TILE_BYTES / 16; i += NTH) {
        uint32_t o = (uint32_t)i * 16;
        CP16(dst + o, kh + o);
        CP16(dst + TILE_BYTES + o, vh + o);
    }
}

// ---------------- main fused kernel ----------------
__global__ __launch_bounds__(NTH, 1)
void attn_hmma(float* __restrict__ O) {
    extern __shared__ char smem[];
    const uint32_t sb = smem_u32(smem);
    const int tid = threadIdx.x, lane = tid & 31, w = tid >> 5;
    const int b = blockIdx.y, t = blockIdx.x;
    const int wm = w >> 1, wn = w & 1;          // wm 0..7, wn 0..1
    const int g = lane >> 2, tig = lane & 3;
    const int m0 = wm * 16;            // warp's local row base (rows m0..m0+15)
    const int nb = wn * 64;            // warp's key base within tile
    const uint32_t ones2[2] = {0x3C003C00u, 0x3C003C00u};   // fp16 {1,1}

    // prologue: Q + first tile's KV
    {
        size_t qb = (size_t)(b * NT + t) * TILE_ELEMS;
        const char* qh = (const char*)(g_h[0] + qb);
        #pragma unroll
        for (int i = tid; i < TILE_BYTES / 16; i += NTH) {
            uint32_t o = (uint32_t)i * 16;
            CP16(sb + SM_QH + o, qh + o);
        }
        fetch_kv(sb + KVBUF(0), b, t, tid);     // seq[0] = t
        CPCOMMIT();
    }

    float oacc[8][4];
    float lacc[4];
    #pragma unroll
    for (int n = 0; n < 8; n++)
        #pragma unroll
        for (int c = 0; c < 4; c++) oacc[n][c] = 0.f;
    #pragma unroll
    for (int c = 0; c < 4; c++) lacc[c] = 0.f;

    #pragma unroll 1
    for (int ii = 0; ii <= NT; ii++) {
        const int j = (ii < NT - t) ? (t + ii) : (ii - (NT - t));
        if (ii < NT) {
            const int jn = (ii + 1 < NT - t) ? (t + ii + 1) : (ii + 1 - (NT - t));
            fetch_kv(sb + KVBUF((ii + 1) & 1), b, jn, tid);
            CPCOMMIT();
            CPWAIT1();
        } else {
            CPWAIT0();
        }
        __syncthreads();                       // tile ii KV ready, prev buffer free
        const uint32_t kb = sb + KVBUF(ii & 1);

        // ---- S = Q @ K^T (single fp16) ----
        float sacc[8][4];
        #pragma unroll
        for (int n = 0; n < 8; n++)
            #pragma unroll
            for (int c = 0; c < 4; c++) sacc[n][c] = 0.f;

        #pragma unroll
        for (int kk = 0; kk < 4; kk++) {
            uint32_t qfr[4];
            ldsm4(qfr, addrP1(sb + SM_QH, m0, 2 * kk, lane));
            uint32_t kf[4][4];
            #pragma unroll
            for (int p = 0; p < 4; p++)
                ldsm4(kf[p], addrP2(kb, nb + p * 16, 2 * kk, lane));
            #pragma unroll
            for (int p = 0; p < 4; p++)
                #pragma unroll
                for (int s = 0; s < 2; s++)
                    mma16816(sacc[p * 2 + s], qfr, &kf[p][s * 2]);
        }

        // ---- mask + pack to fp16 + f16x2 exp2 (P stays in registers) ----
        const int mdir = (j == t) ? ((ii < NT - t) ? 1 : 2) : 0;   // 1=fw diag, 2=bw diag
        uint32_t ph[8][2];
        {
            const int lr = m0 + g;
            #pragma unroll
            for (int n = 0; n < 8; n++) {
                const int lc = nb + n * 8 + 2 * tig;
                float p0 = sacc[n][0], p1 = sacc[n][1];
                float p2 = sacc[n][2], p3 = sacc[n][3];
                if (mdir == 1) {        // fw: zero strictly-lower (col < row)
                    if (lc < lr)         p0 = -1e5f;
                    if (lc + 1 < lr)     p1 = -1e5f;
                    if (lc < lr + 8)     p2 = -1e5f;
                    if (lc + 1 < lr + 8) p3 = -1e5f;
                } else if (mdir == 2) { // bw: zero strictly-upper (col > row)
                    if (lc > lr)         p0 = -1e5f;
                    if (lc + 1 > lr)     p1 = -1e5f;
                    if (lc > lr + 8)     p2 = -1e5f;
                    if (lc + 1 > lr + 8) p3 = -1e5f;
                }
                ph[n][0] = ex2h2(pkh2(p0, p1));   // -1e5 -> fp16 -inf -> ex2 = 0
                ph[n][1] = ex2h2(pkh2(p2, p3));
            }
        }

        // ---- O += P @ V and l += P @ 1 (ones-MMA, no shuffles) ----
        #pragma unroll
        for (int k2 = 0; k2 < 4; k2++) {
            uint32_t vf[4][4];
            #pragma unroll
            for (int p = 0; p < 4; p++)
                ldsm4t(vf[p], addrP1(kb + TILE_BYTES, nb + k2 * 16, 2 * p, lane));
            uint32_t ah[4] = {ph[2 * k2][0], ph[2 * k2][1],
                              ph[2 * k2 + 1][0], ph[2 * k2 + 1][1]};
            #pragma unroll
            for (int p = 0; p < 4; p++)
                #pragma unroll
                for (int s = 0; s < 2; s++)
                    mma16816(oacc[p * 2 + s], ah, &vf[p][s * 2]);
            mma16816(lacc, ah, ones2);       // row sums: lacc[0]=row g, lacc[2]=row g+8
        }

        // ---- phase epilogue ----
        if (ii == NT - 1 - t || ii == NT) {
            const bool addmode = (ii == NT);
            float* lbuf = (float*)(smem + SM_LBUF);
            if (tig == 0) {
                lbuf[wn * 128 + m0 + g] = lacc[0];
                lbuf[wn * 128 + m0 + g + 8] = lacc[2];
            }
            float* obuf = (float*)(smem + SM_OBUF);
            __syncthreads();
            if (wn == 1) {      // n-half 1 dumps its partial O
                #pragma unroll
                for (int n = 0; n < 8; n++) {
                    const int d = n * 8 + 2 * tig;
                    *(float2*)&obuf[(m0 + g) * 64 + d]     = make_float2(oacc[n][0], oacc[n][1]);
                    *(float2*)&obuf[(m0 + g + 8) * 64 + d] = make_float2(oacc[n][2], oacc[n][3]);
                }
            }
            __syncthreads();
            if (wn == 0) {      // n-half 0 combines, normalizes, writes gmem
                const int rr0 = m0 + g, rr1 = rr0 + 8;
                const float inv0 = 1.f / (lbuf[rr0] + lbuf[128 + rr0]);
                const float inv1 = 1.f / (lbuf[rr1] + lbuf[128 + rr1]);
                #pragma unroll
                for (int n = 0; n < 8; n++) {
                    const int d = n * 8 + 2 * tig;
                    float2 e0 = *(float2*)&obuf[rr0 * 64 + d];
                    float2 e1 = *(float2*)&obuf[rr1 * 64 + d];
                    float r0 = (oacc[n][0] + e0.x) * inv0;
                    float r1 = (oacc[n][1] + e0.y) * inv0;
                    float r2 = (oacc[n][2] + e1.x) * inv1;
                    float r3 = (oacc[n][3] + e1.y) * inv1;
                    float2* g0 = (float2*)(O + ((size_t)b * Ln + t * BT + rr0) * Dn + d);
                    float2* g1 = (float2*)(O + ((size_t)b * Ln + t * BT + rr1) * Dn + d);
                    if (addmode) {
                        float2 q0 = *g0, q1 = *g1;
                        *g0 = make_float2(q0.x + r0, q0.y + r1);
                        *g1 = make_float2(q1.x + r2, q1.y + r3);
                    } else {
                        *g0 = make_float2(r0, r1);
                        *g1 = make_float2(r2, r3);
                    }
                }
            }
            if (!addmode) {     // reset accumulators for phase 1
                #pragma unroll
                for (int n = 0; n < 8; n++)
                    #pragma unroll
                    for (int c = 0; c < 4; c++) oacc[n][c] = 0.f;
                #pragma unroll
                for (int c = 0; c < 4; c++) lacc[c] = 0.f;
            }
        }
        __syncthreads();        // all reads of buf[ii&1] done before it is refilled
    }
}

extern "C" void kernel_launch(void* const* d_in, const int* in_sizes, int n_in,
                              void* d_out, int out_size) {
    const float* q = (const float*)d_in[0];
    const float* k = (const float*)d_in[1];
    const float* v = (const float*)d_in[2];
    float* o = (float*)d_out;

    // 16B-chunks per tensor = Bn*Ln*Dn/8 = 131072 -> 512 blocks x 256 threads
    dim3 pg((Bn * Ln * Dn) / 8 / 256, 3);
    prep_kernel<<<pg, 256>>>(q, k, v);

    cudaFuncSetAttribute(attn_hmma,
                         cudaFuncAttributeMaxDynamicSharedMemorySize, SMEM_TOTAL);
    dim3 grid(NT, Bn);
    attn_hmma<<<grid, NTH, SMEM_TOTAL>>>(o);
}

// round 10
// speedup vs baseline: 12.0603x; 1.0250x over previous
#include <cuda_runtime.h>
#include <cuda_fp16.h>
#include <stdint.h>

#define Bn 8
#define Ln 2048
#define Dn 64
#define BT 128
#define NT 16
#define NTH 512
#define TILE_ELEMS (BT * Dn)          // 8192
#define TILE_BYTES (TILE_ELEMS * 2)   // 16384

// fp16 scratch: [0]=Q(prescaled by 0.125*log2e), [1]=K, [2]=V; SW128-swizzled tile blobs
__device__ __align__(256) __half g_h[3][Bn * Ln * Dn];

__host__ __device__ __forceinline__ uint32_t sw128(uint32_t x) {
    return x ^ ((x >> 3) & 0x70);
}

// ---------------- smem layout (bytes) ----------------
#define SM_QH 0
#define SM_KV TILE_BYTES                        // 4 ring bufs x {Kh, Vh}
#define KVBUF(i) (SM_KV + (uint32_t)(i) * 2u * TILE_BYTES)
#define SM_OBUF (SM_KV + 8 * TILE_BYTES)        // 147456: 128*64 floats = 32768 B
#define SM_LBUF (SM_OBUF + 32768)               // 180224: 2*128 floats
#define SMEM_TOTAL (SM_LBUF + 1024)             // 181248

// ---------------- asm helpers (base ISA, compute_103-safe) ----------------
__device__ __forceinline__ uint32_t smem_u32(const void* p) {
    uint32_t a;
    asm("{ .reg .u64 t; cvta.to.shared.u64 t, %1; cvt.u32.u64 %0, t; }" : "=r"(a) : "l"(p));
    return a;
}
#define CP16(dst, src) \
    asm volatile("cp.async.cg.shared.global [%0], [%1], 16;" :: "r"(dst), "l"(src))
#define CPCOMMIT() asm volatile("cp.async.commit_group;" ::: "memory")
#define CPWAIT1()  asm volatile("cp.async.wait_group 1;" ::: "memory")
#define CPWAIT0()  asm volatile("cp.async.wait_group 0;" ::: "memory")

__device__ __forceinline__ void ldsm4(uint32_t* r, uint32_t a) {
    asm volatile("ldmatrix.sync.aligned.m8n8.x4.shared.b16 {%0,%1,%2,%3}, [%4];"
                 : "=r"(r[0]), "=r"(r[1]), "=r"(r[2]), "=r"(r[3]) : "r"(a));
}
__device__ __forceinline__ void ldsm4t(uint32_t* r, uint32_t a) {
    asm volatile("ldmatrix.sync.aligned.m8n8.x4.trans.shared.b16 {%0,%1,%2,%3}, [%4];"
                 : "=r"(r[0]), "=r"(r[1]), "=r"(r[2]), "=r"(r[3]) : "r"(a));
}
__device__ __forceinline__ void mma16816(float* c, const uint32_t* a, const uint32_t* b) {
    asm volatile("mma.sync.aligned.m16n8k16.row.col.f32.f16.f16.f32 "
                 "{%0,%1,%2,%3}, {%4,%5,%6,%7}, {%8,%9}, {%0,%1,%2,%3};"
                 : "+f"(c[0]), "+f"(c[1]), "+f"(c[2]), "+f"(c[3])
                 : "r"(a[0]), "r"(a[1]), "r"(a[2]), "r"(a[3]), "r"(b[0]), "r"(b[1]));
}
// pack two fp32 to half2 (bits), then exp2 on both halves in one MUFU op
__device__ __forceinline__ uint32_t pkh2(float lo, float hi) {
    __half2 h = __floats2half2_rn(lo, hi);
    return *reinterpret_cast<uint32_t*>(&h);
}
__device__ __forceinline__ uint32_t ex2h2(uint32_t x) {
    uint32_t r;
    asm("ex2.approx.f16x2 %0, %1;" : "=r"(r) : "r"(x));
    return r;
}

// swizzled address of (row, 16B-chunk) in a 128x64 fp16 tile blob
__device__ __forceinline__ uint32_t taddr(uint32_t base, int row, int ch) {
    return base + ((uint32_t)row << 7) + (uint32_t)((ch ^ (row & 7)) << 4);
}
// pattern P1 (A-frag / V trans-frag): groups {r0,c0},{r0+8,c0},{r0,c0+1},{r0+8,c0+1}
__device__ __forceinline__ uint32_t addrP1(uint32_t base, int r0, int c0, int lane) {
    int grp = lane >> 3;
    return taddr(base, r0 + (grp & 1) * 8 + (lane & 7), c0 + (grp >> 1));
}
// pattern P2 (K B-frag): groups {r0,c0},{r0,c0+1},{r0+8,c0},{r0+8,c0+1}
__device__ __forceinline__ uint32_t addrP2(uint32_t base, int r0, int c0, int lane) {
    int grp = lane >> 3;
    return taddr(base, r0 + (grp >> 1) * 8 + (lane & 7), c0 + (grp & 1));
}

// ---------------- prepass: fp32 -> fp16, swizzled tile blobs (8 elems/thread) ----------------
__global__ void prep_kernel(const float* __restrict__ q, const float* __restrict__ k,
                            const float* __restrict__ v) {
    const int t = blockIdx.y;
    const float* src = (t == 0) ? q : (t == 1) ? k : v;
    const float sc = (t == 0) ? (0.125f * 1.44269504088896f) : 1.f;  // fold 1/8 and log2e into Q
    uint32_t i8 = blockIdx.x * blockDim.x + threadIdx.x;   // 16B-chunk index
    uint32_t c   = i8 & 7;                 // d-chunk (8 halves per chunk)
    uint32_t row = (i8 >> 3) & (Ln - 1);
    uint32_t b   = i8 >> 14;
    const float4* s4 = reinterpret_cast<const float4*>(src + ((size_t)(b * Ln + row)) * Dn + c * 8);
    float4 x0 = s4[0], x1 = s4[1];
    uint32_t h0 = pkh2(x0.x * sc, x0.y * sc);
    uint32_t h1 = pkh2(x0.z * sc, x0.w * sc);
    uint32_t h2 = pkh2(x1.x * sc, x1.y * sc);
    uint32_t h3 = pkh2(x1.z * sc, x1.w * sc);
    uint32_t tile = row >> 7, r = row & 127;
    uint32_t off = sw128(r * 128 + c * 16);
    uint4* dst = reinterpret_cast<uint4*>(
        reinterpret_cast<char*>(g_h[t] + (size_t)(b * NT + tile) * TILE_ELEMS) + off);
    *dst = make_uint4(h0, h1, h2, h3);
}

__device__ __forceinline__ void fetch_kv(uint32_t dst, int b, int j, int tid) {
    size_t blob = (size_t)(b * NT + j) * TILE_ELEMS;
    const char* kh = (const char*)(g_h[1] + blob);
    const char* vh = (const char*)(g_h[2] + blob);
    #pragma unroll
    for (int i = tid; i < TILE_BYTES / 16; i += NTH) {
        uint32_t o = (uint32_t)i * 16;
        CP16(dst + o, kh + o);
        CP16(dst + TILE_BYTES + o, vh + o);
    }
}

// tile-visit order: ii=0..15 -> j = t..15, 0..t-1 ; ii=16 -> j=t (bw diag pass)
__device__ __forceinline__ int seqj(int ii, int t) {
    return (ii < NT - t) ? (t + ii) : (ii - (NT - t));
}

// ---------------- main fused kernel ----------------
__global__ __launch_bounds__(NTH, 1)
void attn_hmma(float* __restrict__ O) {
    extern __shared__ char smem[];
    const uint32_t sb = smem_u32(smem);
    const int tid = threadIdx.x, lane = tid & 31, w = tid >> 5;
    const int b = blockIdx.y, t = blockIdx.x;
    const int wm = w >> 1, wn = w & 1;          // wm 0..7, wn 0..1
    const int g = lane >> 2, tig = lane & 3;
    const int m0 = wm * 16;            // warp's local row base (rows m0..m0+15)
    const int nb = wn * 64;            // warp's key base within tile
    const uint32_t ones2[2] = {0x3C003C00u, 0x3C003C00u};   // fp16 {1,1}

    // prologue: Q + KV(0) (group 0), KV(1) (group 1)
    {
        size_t qb = (size_t)(b * NT + t) * TILE_ELEMS;
        const char* qh = (const char*)(g_h[0] + qb);
        #pragma unroll
        for (int i = tid; i < TILE_BYTES / 16; i += NTH) {
            uint32_t o = (uint32_t)i * 16;
            CP16(sb + SM_QH + o, qh + o);
        }
        fetch_kv(sb + KVBUF(0), b, seqj(0, t), tid);
        CPCOMMIT();
        fetch_kv(sb + KVBUF(1), b, seqj(1, t), tid);
        CPCOMMIT();
    }

    float oacc[8][4];
    float lacc[4];
    #pragma unroll
    for (int n = 0; n < 8; n++)
        #pragma unroll
        for (int c = 0; c < 4; c++) oacc[n][c] = 0.f;
    #pragma unroll
    for (int c = 0; c < 4; c++) lacc[c] = 0.f;

    uint32_t ph[8][2];
    float sacc[8][4];

    CPWAIT1();               // group 0 (Q + KV(0)) complete
    __syncthreads();

    // ---- S(0) + exp -> ph(0); tile 0 is always the fw diagonal (mdir=1) ----
    {
        const uint32_t kb = sb + KVBUF(0);
        #pragma unroll
        for (int n = 0; n < 8; n++)
            #pragma unroll
            for (int c = 0; c < 4; c++) sacc[n][c] = 0.f;
        #pragma unroll
        for (int kk = 0; kk < 4; kk++) {
            uint32_t qfr[4];
            ldsm4(qfr, addrP1(sb + SM_QH, m0, 2 * kk, lane));
            uint32_t kf[4][4];
            #pragma unroll
            for (int p = 0; p < 4; p++)
                ldsm4(kf[p], addrP2(kb, nb + p * 16, 2 * kk, lane));
            #pragma unroll
            for (int p = 0; p < 4; p++)
                #pragma unroll
                for (int s = 0; s < 2; s++)
                    mma16816(sacc[p * 2 + s], qfr, &kf[p][s * 2]);
        }
        const int lr = m0 + g;
        #pragma unroll
        for (int n = 0; n < 8; n++) {
            const int lc = nb + n * 8 + 2 * tig;
            float p0 = sacc[n][0], p1 = sacc[n][1];
            float p2 = sacc[n][2], p3 = sacc[n][3];
            if (lc < lr)         p0 = -1e5f;
            if (lc + 1 < lr)     p1 = -1e5f;
            if (lc < lr + 8)     p2 = -1e5f;
            if (lc + 1 < lr + 8) p3 = -1e5f;
            ph[n][0] = ex2h2(pkh2(p0, p1));
            ph[n][1] = ex2h2(pkh2(p2, p3));
        }
    }

    // ---- pipelined mainloop: QK(ii+1) || PV(ii), exp(ii+1) overlapped ----
    #pragma unroll 1
    for (int ii = 0; ii <= NT; ii++) {
        if (ii <= NT - 2) {
            fetch_kv(sb + KVBUF((ii + 2) & 3), b, seqj(ii + 2, t), tid);
            CPCOMMIT();
            CPWAIT1();       // KV(ii+1) complete (only KV(ii+2) may remain in flight)
        } else {
            CPWAIT0();
        }
        __syncthreads();     // KV(ii+1) visible to all; everyone done with buf[(ii+3)&3]

        // ---- S(ii+1) = Q @ K(ii+1)^T (skipped on the last iteration) ----
        if (ii < NT) {
            const uint32_t kb = sb + KVBUF((ii + 1) & 3);
            #pragma unroll
            for (int n = 0; n < 8; n++)
                #pragma unroll
                for (int c = 0; c < 4; c++) sacc[n][c] = 0.f;
            #pragma unroll
            for (int kk = 0; kk < 4; kk++) {
                uint32_t qfr[4];
                ldsm4(qfr, addrP1(sb + SM_QH, m0, 2 * kk, lane));
                uint32_t kf[4][4];
                #pragma unroll
                for (int p = 0; p < 4; p++)
                    ldsm4(kf[p], addrP2(kb, nb + p * 16, 2 * kk, lane));
                #pragma unroll
                for (int p = 0; p < 4; p++)
                    #pragma unroll
                    for (int s = 0; s < 2; s++)
                        mma16816(sacc[p * 2 + s], qfr, &kf[p][s * 2]);
            }
        }

        // ---- PV(ii): O += P @ V, l += P @ 1 (V from buf ii&3, ph from prev stage) ----
        {
            const uint32_t vb = sb + KVBUF(ii & 3) + TILE_BYTES;
            #pragma unroll
            for (int k2 = 0; k2 < 4; k2++) {
                uint32_t vf[4][4];
                #pragma unroll
                for (int p = 0; p < 4; p++)
                    ldsm4t(vf[p], addrP1(vb, nb + k2 * 16, 2 * p, lane));
                uint32_t ah[4] = {ph[2 * k2][0], ph[2 * k2][1],
                                  ph[2 * k2 + 1][0], ph[2 * k2 + 1][1]};
                #pragma unroll
                for (int p = 0; p < 4; p++)
                    #pragma unroll
                    for (int s = 0; s < 2; s++)
                        mma16816(oacc[p * 2 + s], ah, &vf[p][s * 2]);
                mma16816(lacc, ah, ones2);
            }
        }

        // ---- exp(ii+1): sacc -> ph (MUFU overlaps PV drain) ----
        if (ii < NT) {
            const int j2 = seqj(ii + 1, t);
            const int mdir = (j2 == t) ? ((ii + 1 < NT - t) ? 1 : 2) : 0;
            const int lr = m0 + g;
            #pragma unroll
            for (int n = 0; n < 8; n++) {
                const int lc = nb + n * 8 + 2 * tig;
                float p0 = sacc[n][0], p1 = sacc[n][1];
                float p2 = sacc[n][2], p3 = sacc[n][3];
                if (mdir == 1) {
                    if (lc < lr)         p0 = -1e5f;
                    if (lc + 1 < lr)     p1 = -1e5f;
                    if (lc < lr + 8)     p2 = -1e5f;
                    if (lc + 1 < lr + 8) p3 = -1e5f;
                } else if (mdir == 2) {
                    if (lc > lr)         p0 = -1e5f;
                    if (lc + 1 > lr)     p1 = -1e5f;
                    if (lc > lr + 8)     p2 = -1e5f;
                    if (lc + 1 > lr + 8) p3 = -1e5f;
                }
                ph[n][0] = ex2h2(pkh2(p0, p1));
                ph[n][1] = ex2h2(pkh2(p2, p3));
            }
        }

        // ---- phase epilogue (after PV of last tile of each direction) ----
        if (ii == NT - 1 - t || ii == NT) {
            const bool addmode = (ii == NT);
            float* lbuf = (float*)(smem + SM_LBUF);
            if (tig == 0) {
                lbuf[wn * 128 + m0 + g] = lacc[0];
                lbuf[wn * 128 + m0 + g + 8] = lacc[2];
            }
            float* obuf = (float*)(smem + SM_OBUF);
            __syncthreads();
            if (wn == 1) {      // n-half 1 dumps its partial O
                #pragma unroll
                for (int n = 0; n < 8; n++) {
                    const int d = n * 8 + 2 * tig;
                    *(float2*)&obuf[(m0 + g) * 64 + d]     = make_float2(oacc[n][0], oacc[n][1]);
                    *(float2*)&obuf[(m0 + g + 8) * 64 + d] = make_float2(oacc[n][2], oacc[n][3]);
                }
            }
            __syncthreads();
            if (wn == 0) {      // n-half 0 combines, normalizes, writes gmem
                const int rr0 = m0 + g, rr1 = rr0 + 8;
                const float inv0 = 1.f / (lbuf[rr0] + lbuf[128 + rr0]);
                const float inv1 = 1.f / (lbuf[rr1] + lbuf[128 + rr1]);
                #pragma unroll
                for (int n = 0; n < 8; n++) {
                    const int d = n * 8 + 2 * tig;
                    float2 e0 = *(float2*)&obuf[rr0 * 64 + d];
                    float2 e1 = *(float2*)&obuf[rr1 * 64 + d];
                    float r0 = (oacc[n][0] + e0.x) * inv0;
                    float r1 = (oacc[n][1] + e0.y) * inv0;
                    float r2 = (oacc[n][2] + e1.x) * inv1;
                    float r3 = (oacc[n][3] + e1.y) * inv1;
                    float2* g0 = (float2*)(O + ((size_t)b * Ln + t * BT + rr0) * Dn + d);
                    float2* g1 = (float2*)(O + ((size_t)b * Ln + t * BT + rr1) * Dn + d);
                    if (addmode) {
                        float2 q0 = *g0, q1 = *g1;
                        *g0 = make_float2(q0.x + r0, q0.y + r1);
                        *g1 = make_float2(q1.x + r2, q1.y + r3);
                    } else {
                        *g0 = make_float2(r0, r1);
                        *g1 = make_float2(r2, r3);
                    }
                }
            }
            if (!addmode) {     // reset accumulators for the bw phase
                #pragma unroll
                for (int n = 0; n < 8; n++)
                    #pragma unroll
                    for (int c = 0; c < 4; c++) oacc[n][c] = 0.f;
                #pragma unroll
                for (int c = 0; c < 4; c++) lacc[c] = 0.f;
            }
        }
    }
}

extern "C" void kernel_launch(void* const* d_in, const int* in_sizes, int n_in,
                              void* d_out, int out_size) {
    const float* q = (const float*)d_in[0];
    const float* k = (const float*)d_in[1];
    const float* v = (const float*)d_in[2];
    float* o = (float*)d_out;

    // 16B-chunks per tensor = Bn*Ln*Dn/8 = 131072 -> 512 blocks x 256 threads
    dim3 pg((Bn * Ln * Dn) / 8 / 256, 3);
    prep_kernel<<<pg, 256>>>(q, k, v);

    cudaFuncSetAttribute(attn_hmma,
                         cudaFuncAttributeMaxDynamicSharedMemorySize, SMEM_TOTAL);
    dim3 grid(NT, Bn);
    attn_hmma<<<grid, NTH, SMEM_TOTAL>>>(o);
}